// round 15
// baseline (speedup 1.0000x reference)
#include <cuda_runtime.h>
#include <cuda_bf16.h>
#include <cuda_fp16.h>
#include <stdint.h>
#include <math.h>

#define BB 4
#define CC 512
#define HW 4096
#define GROUPS 32
#define GSIZE 16

// ---------------- scratch ----------------
__device__ __half        g_s [(size_t)BB * HW * HW];
__device__ __nv_bfloat16 g_hnh[(size_t)BB * CC * HW];
__device__ __nv_bfloat16 g_hnl[(size_t)BB * CC * HW];
__device__ __nv_bfloat16 g_hh[(size_t)BB * CC * HW];
__device__ __nv_bfloat16 g_hl[(size_t)BB * CC * HW];
__device__ __nv_bfloat16 g_qc[(size_t)BB * HW * CC];
__device__ __nv_bfloat16 g_kc[(size_t)BB * HW * CC];
__device__ __nv_bfloat16 g_vc[(size_t)BB * CC * HW];
__device__ __nv_bfloat16 g_wc[(size_t)BB * HW * HW];
__device__ __nv_bfloat16 g_wh[4][CC * CC];   // wq,wk,wv (stacked, rows 0..1535), wp
__device__ __nv_bfloat16 g_wl[4][CC * CC];

// ---------------- streams/events ----------------
struct StreamPack {
    cudaStream_t s[4];
    cudaEvent_t evFork, evGN, evW[4], evJoin[4];
    StreamPack() {
        for (int i = 0; i < 4; i++) cudaStreamCreateWithFlags(&s[i], cudaStreamNonBlocking);
        cudaEventCreateWithFlags(&evFork, cudaEventDisableTiming);
        cudaEventCreateWithFlags(&evGN, cudaEventDisableTiming);
        for (int i = 0; i < 4; i++) cudaEventCreateWithFlags(&evW[i], cudaEventDisableTiming);
        for (int i = 0; i < 4; i++) cudaEventCreateWithFlags(&evJoin[i], cudaEventDisableTiming);
    }
};
static StreamPack g_sp;

__device__ __forceinline__ uint32_t smem_u32(const void* p) {
    return (uint32_t)__cvta_generic_to_shared(p);
}
__device__ __forceinline__ void cp16(uint32_t dst, const void* src) {
    asm volatile("cp.async.cg.shared.global [%0], [%1], 16;" :: "r"(dst), "l"(src));
}
__device__ __forceinline__ uint32_t bf16pair(float a, float b) {
    return (uint32_t)__bfloat16_as_ushort(__float2bfloat16(a)) |
           ((uint32_t)__bfloat16_as_ushort(__float2bfloat16(b)) << 16);
}
__device__ __forceinline__ void split_pack2(float a0, float a1, uint32_t& hi, uint32_t& lo) {
    __nv_bfloat16 h0 = __float2bfloat16(a0);
    __nv_bfloat16 h1 = __float2bfloat16(a1);
    __nv_bfloat16 l0 = __float2bfloat16(a0 - __bfloat162float(h0));
    __nv_bfloat16 l1 = __float2bfloat16(a1 - __bfloat162float(h1));
    hi = (uint32_t)__bfloat16_as_ushort(h0) | ((uint32_t)__bfloat16_as_ushort(h1) << 16);
    lo = (uint32_t)__bfloat16_as_ushort(l0) | ((uint32_t)__bfloat16_as_ushort(l1) << 16);
}

// ---------------- weight split ----------------
__global__ __launch_bounds__(256) void wsplit_k(
    const float* __restrict__ src, __nv_bfloat16* __restrict__ hi,
    __nv_bfloat16* __restrict__ lo, int n)
{
    const int i = (blockIdx.x * 256 + threadIdx.x) * 4;
    if (i >= n) return;
    float4 t = *(const float4*)(src + i);
    uint32_t h01, l01, h23, l23;
    split_pack2(t.x, t.y, h01, l01);
    split_pack2(t.z, t.w, h23, l23);
    *(uint2*)(hi + i) = make_uint2(h01, h23);
    *(uint2*)(lo + i) = make_uint2(l01, l23);
}

// ---------------- GroupNorm -> bf16 hi/lo ----------------
__global__ __launch_bounds__(256) void gn_kernel(
    const float* __restrict__ x, const float* __restrict__ gamma,
    const float* __restrict__ beta,
    __nv_bfloat16* __restrict__ oh, __nv_bfloat16* __restrict__ ol)
{
    const int b = blockIdx.x >> 5;
    const int g = blockIdx.x & 31;
    const size_t base = ((size_t)b * CC + (size_t)g * GSIZE) * HW;
    const int LEN4 = (GSIZE * HW) / 4;
    const float4* __restrict__ xin = (const float4*)(x + base);

    float s = 0.f, s2 = 0.f;
    for (int i = threadIdx.x; i < LEN4; i += 256) {
        float4 t = xin[i];
        s  += t.x + t.y + t.z + t.w;
        s2 += t.x * t.x + t.y * t.y + t.z * t.z + t.w * t.w;
    }
    __shared__ float wr1[8], wr2[8];
    __shared__ float s_mu, s_rstd;
    for (int o = 16; o; o >>= 1) {
        s  += __shfl_xor_sync(0xffffffffu, s,  o);
        s2 += __shfl_xor_sync(0xffffffffu, s2, o);
    }
    const int warp = threadIdx.x >> 5, lane = threadIdx.x & 31;
    if (lane == 0) { wr1[warp] = s; wr2[warp] = s2; }
    __syncthreads();
    if (threadIdx.x == 0) {
        float ts = 0.f, ts2 = 0.f;
        #pragma unroll
        for (int i = 0; i < 8; i++) { ts += wr1[i]; ts2 += wr2[i]; }
        const float inv_n = 1.0f / (float)(GSIZE * HW);
        float mu  = ts * inv_n;
        float var = ts2 * inv_n - mu * mu;
        s_mu = mu;
        s_rstd = 1.0f / sqrtf(var + 1e-6f);
    }
    __syncthreads();
    const float mu = s_mu, rstd = s_rstd;

    for (int i = threadIdx.x; i < LEN4; i += 256) {
        float4 t = xin[i];
        const int c = g * GSIZE + ((i * 4) >> 12);
        const float ga = gamma[c] * rstd, be = beta[c];
        t.x = (t.x - mu) * ga + be;
        t.y = (t.y - mu) * ga + be;
        t.z = (t.z - mu) * ga + be;
        t.w = (t.w - mu) * ga + be;
        uint32_t h01, l01, h23, l23;
        split_pack2(t.x, t.y, h01, l01);
        split_pack2(t.z, t.w, h23, l23);
        *(uint2*)(oh + base + (size_t)i * 4) = make_uint2(h01, h23);
        *(uint2*)(ol + base + (size_t)i * 4) = make_uint2(l01, l23);
    }
}

// ---------------- common bf16x3 mainloop macro pieces ----------------
#define A_ROWB 80
#define B_ROWB 272
#define ABYTES (128 * A_ROWB)
#define BBYTES (32 * B_ROWB)
#define BUFB   (2 * ABYTES + 2 * BBYTES)
#define SMEM_BF16 (3 * BUFB)

// ---------------- fused QKV projection GEMM ----------------
// Stacked weights Ah/Al: [3*CC, CC]. grid = (HW/128, 12). by>>2 selects q/k/v.
__global__ __launch_bounds__(256, 2) void qkv_gemm_k(
    const __nv_bfloat16* __restrict__ Ah_g, const __nv_bfloat16* __restrict__ Al_g,
    const __nv_bfloat16* __restrict__ Bh_g, const __nv_bfloat16* __restrict__ Bl_g,
    __nv_bfloat16* __restrict__ Qc, __nv_bfloat16* __restrict__ Kc, __nv_bfloat16* __restrict__ Vc,
    const float* __restrict__ bq, const float* __restrict__ bk, const float* __restrict__ bv,
    const float* __restrict__ dq, const float* __restrict__ zq,
    const float* __restrict__ dk, const float* __restrict__ zk,
    const float* __restrict__ dv, const float* __restrict__ zv)
{
    extern __shared__ char sm[];
    const uint32_t smb = smem_u32(sm);

    const int K = CC, N = HW, M = CC;
    const int by = blockIdx.y;
    const int p = by >> 2;               // 0=q, 1=k, 2=v
    const int bm = by * 128;             // row into stacked weights
    const int bmL = (by & 3) * 128;      // row into this projection
    const int bn = blockIdx.x * 128;
    const int tid = threadIdx.x;
    const int w = tid >> 5, lane = tid & 31;
    const int wm = w >> 2, wn = w & 3;
    const int grp = lane >> 2, tig = lane & 3;

    float acc[4][4][4];
    #pragma unroll
    for (int a = 0; a < 4; a++)
        #pragma unroll
        for (int b = 0; b < 4; b++)
            #pragma unroll
            for (int c = 0; c < 4; c++) acc[a][b][c] = 0.f;

    const uint32_t a_lane = (uint32_t)(lane & 15) * A_ROWB + (uint32_t)(lane >> 4) * 16;
    const uint32_t b_lane = (uint32_t)(lane & 15) * B_ROWB;

    const int nst = K >> 5;

#define PJ_FILL(ST) do {                                                       \
        const uint32_t _b = smb + (uint32_t)((ST) % 3) * BUFB;                 \
        const int _k0 = (ST) << 5;                                             \
        _Pragma("unroll")                                                      \
        for (int _j = 0; _j < 2; _j++) {                                       \
            const int _id = tid + 256 * _j;                                    \
            const int _ar = _id >> 2, _as = _id & 3;                           \
            const size_t _ag = (size_t)(bm + _ar) * K + _k0 + _as * 8;         \
            cp16(_b + (uint32_t)(_ar * A_ROWB + _as * 16), Ah_g + _ag);        \
            cp16(_b + ABYTES + (uint32_t)(_ar * A_ROWB + _as * 16), Al_g + _ag); \
            const int _br = _id >> 4, _bs = _id & 15;                          \
            const size_t _bg = (size_t)(_k0 + _br) * N + bn + _bs * 8;         \
            cp16(_b + 2 * ABYTES + (uint32_t)(_br * B_ROWB + _bs * 16), Bh_g + _bg); \
            cp16(_b + 2 * ABYTES + BBYTES + (uint32_t)(_br * B_ROWB + _bs * 16), Bl_g + _bg); \
        }                                                                      \
    } while (0)

    PJ_FILL(0);
    asm volatile("cp.async.commit_group;");
    if (nst > 1) PJ_FILL(1);
    asm volatile("cp.async.commit_group;");

    for (int st = 0; st < nst; st++) {
        asm volatile("cp.async.wait_group 1;");
        __syncthreads();
        if (st + 2 < nst) PJ_FILL(st + 2);
        asm volatile("cp.async.commit_group;");

        const uint32_t aho = smb + (uint32_t)(st % 3) * BUFB;
        const uint32_t bho = aho + 2 * ABYTES;

        #pragma unroll
        for (int kc = 0; kc < 2; kc++) {
            uint32_t bhf[4][2], blf[4][2];
            #pragma unroll
            for (int fn = 0; fn < 4; fn++) {
                const uint32_t addr = bho + kc * 16 * B_ROWB + b_lane + (uint32_t)(wn * 64 + fn * 16);
                asm volatile("ldmatrix.sync.aligned.m8n8.x2.trans.shared.b16 {%0,%1},[%2];"
                             : "=r"(bhf[fn][0]), "=r"(bhf[fn][1]) : "r"(addr));
                asm volatile("ldmatrix.sync.aligned.m8n8.x2.trans.shared.b16 {%0,%1},[%2];"
                             : "=r"(blf[fn][0]), "=r"(blf[fn][1]) : "r"(addr + BBYTES));
            }
            #pragma unroll
            for (int fm = 0; fm < 4; fm++) {
                const uint32_t aaddr = aho + (uint32_t)((wm * 64 + fm * 16) * A_ROWB) + kc * 32 + a_lane;
                uint32_t ah[4], al[4];
                asm volatile("ldmatrix.sync.aligned.m8n8.x4.shared.b16 {%0,%1,%2,%3},[%4];"
                             : "=r"(ah[0]), "=r"(ah[1]), "=r"(ah[2]), "=r"(ah[3]) : "r"(aaddr));
                asm volatile("ldmatrix.sync.aligned.m8n8.x4.shared.b16 {%0,%1,%2,%3},[%4];"
                             : "=r"(al[0]), "=r"(al[1]), "=r"(al[2]), "=r"(al[3]) : "r"(aaddr + ABYTES));
                #pragma unroll
                for (int fn = 0; fn < 4; fn++) {
                    float* d = acc[fm][fn];
                    asm volatile(
                        "mma.sync.aligned.m16n8k16.row.col.f32.bf16.bf16.f32 "
                        "{%0,%1,%2,%3},{%4,%5,%6,%7},{%8,%9},{%0,%1,%2,%3};\n"
                        : "+f"(d[0]), "+f"(d[1]), "+f"(d[2]), "+f"(d[3])
                        : "r"(ah[0]), "r"(ah[1]), "r"(ah[2]), "r"(ah[3]),
                          "r"(bhf[fn][0]), "r"(bhf[fn][1]));
                    asm volatile(
                        "mma.sync.aligned.m16n8k16.row.col.f32.bf16.bf16.f32 "
                        "{%0,%1,%2,%3},{%4,%5,%6,%7},{%8,%9},{%0,%1,%2,%3};\n"
                        : "+f"(d[0]), "+f"(d[1]), "+f"(d[2]), "+f"(d[3])
                        : "r"(ah[0]), "r"(ah[1]), "r"(ah[2]), "r"(ah[3]),
                          "r"(blf[fn][0]), "r"(blf[fn][1]));
                    asm volatile(
                        "mma.sync.aligned.m16n8k16.row.col.f32.bf16.bf16.f32 "
                        "{%0,%1,%2,%3},{%4,%5,%6,%7},{%8,%9},{%0,%1,%2,%3};\n"
                        : "+f"(d[0]), "+f"(d[1]), "+f"(d[2]), "+f"(d[3])
                        : "r"(al[0]), "r"(al[1]), "r"(al[2]), "r"(al[3]),
                          "r"(bhf[fn][0]), "r"(bhf[fn][1]));
                }
            }
        }
        __syncthreads();
    }
#undef PJ_FILL

    const float delta = (p == 0) ? *dq : (p == 1) ? *dk : *dv;
    const float zp    = (p == 0) ? *zq : (p == 1) ? *zk : *zv;
    const float* bias = (p == 0) ? bq : (p == 1) ? bk : bv;
    const float invd = 1.0f / delta;

    if (p == 2) {
        // v: natural [C, HW]
        __nv_bfloat16* Cb = Vc;
        #pragma unroll
        for (int fm = 0; fm < 4; fm++) {
            const int r1 = wm * 64 + fm * 16 + grp;
            const int r2 = r1 + 8;
            const float b1v = bias[bmL + r1];
            const float b2v = bias[bmL + r2];
            #pragma unroll
            for (int fn = 0; fn < 4; fn++) {
                const int c = wn * 32 + fn * 8 + tig * 2;
                const float* d = acc[fm][fn];
                float q0 = fminf(fmaxf(rintf((d[0] + b1v) * invd) + zp, 0.f), 255.f) - zp;
                float q1 = fminf(fmaxf(rintf((d[1] + b1v) * invd) + zp, 0.f), 255.f) - zp;
                float q2 = fminf(fmaxf(rintf((d[2] + b2v) * invd) + zp, 0.f), 255.f) - zp;
                float q3 = fminf(fmaxf(rintf((d[3] + b2v) * invd) + zp, 0.f), 255.f) - zp;
                *(uint32_t*)(Cb + (size_t)(bmL + r1) * N + bn + c) = bf16pair(q0, q1);
                *(uint32_t*)(Cb + (size_t)(bmL + r2) * N + bn + c) = bf16pair(q2, q3);
            }
        }
    } else {
        // q/k: transposed [HW, C] via smem staging
        __nv_bfloat16* Cb = (p == 0) ? Qc : Kc;
        __nv_bfloat16* t16 = (__nv_bfloat16*)sm;
        #pragma unroll
        for (int fm = 0; fm < 4; fm++) {
            const int r1 = wm * 64 + fm * 16 + grp;
            const int r2 = r1 + 8;
            const float b1v = bias[bmL + r1];
            const float b2v = bias[bmL + r2];
            #pragma unroll
            for (int fn = 0; fn < 4; fn++) {
                const int c = wn * 32 + fn * 8 + tig * 2;
                const float* d = acc[fm][fn];
                float q0 = fminf(fmaxf(rintf((d[0] + b1v) * invd) + zp, 0.f), 255.f) - zp;
                float q1 = fminf(fmaxf(rintf((d[1] + b1v) * invd) + zp, 0.f), 255.f) - zp;
                float q2 = fminf(fmaxf(rintf((d[2] + b2v) * invd) + zp, 0.f), 255.f) - zp;
                float q3 = fminf(fmaxf(rintf((d[3] + b2v) * invd) + zp, 0.f), 255.f) - zp;
                t16[(c + 0) * 136 + r1] = __float2bfloat16(q0);
                t16[(c + 1) * 136 + r1] = __float2bfloat16(q1);
                t16[(c + 0) * 136 + r2] = __float2bfloat16(q2);
                t16[(c + 1) * 136 + r2] = __float2bfloat16(q3);
            }
        }
        __syncthreads();
        #pragma unroll
        for (int it = 0; it < 8; it++) {
            const int l = tid + 256 * it;
            const int row = l >> 4;
            const int seg = l & 15;
            uint4 val = *(uint4*)(t16 + row * 136 + seg * 8);
            *(uint4*)(Cb + (size_t)(bn + row) * M + bmL + seg * 8) = val;
        }
    }
}

// ---------------- output projection GEMM (bf16x3, f32 out + bias + resid) ----------------
__global__ __launch_bounds__(256, 2) void proj_gemm_k(
    const __nv_bfloat16* __restrict__ Ah_g, const __nv_bfloat16* __restrict__ Al_g,
    const __nv_bfloat16* __restrict__ Bh_g, const __nv_bfloat16* __restrict__ Bl_g,
    float* __restrict__ C, int M, int N, int K,
    const float* __restrict__ bias, const float* __restrict__ resid)
{
    extern __shared__ char sm[];
    const uint32_t smb = smem_u32(sm);

    const int bm = blockIdx.y * 128;
    const int bn = blockIdx.x * 128;
    const int tid = threadIdx.x;
    const int w = tid >> 5, lane = tid & 31;
    const int wm = w >> 2, wn = w & 3;
    const int grp = lane >> 2, tig = lane & 3;

    float acc[4][4][4];
    #pragma unroll
    for (int a = 0; a < 4; a++)
        #pragma unroll
        for (int b = 0; b < 4; b++)
            #pragma unroll
            for (int c = 0; c < 4; c++) acc[a][b][c] = 0.f;

    const uint32_t a_lane = (uint32_t)(lane & 15) * A_ROWB + (uint32_t)(lane >> 4) * 16;
    const uint32_t b_lane = (uint32_t)(lane & 15) * B_ROWB;

    const int nst = K >> 5;

#define PJ_FILL(ST) do {                                                       \
        const uint32_t _b = smb + (uint32_t)((ST) % 3) * BUFB;                 \
        const int _k0 = (ST) << 5;                                             \
        _Pragma("unroll")                                                      \
        for (int _j = 0; _j < 2; _j++) {                                       \
            const int _id = tid + 256 * _j;                                    \
            const int _ar = _id >> 2, _as = _id & 3;                           \
            const size_t _ag = (size_t)(bm + _ar) * K + _k0 + _as * 8;         \
            cp16(_b + (uint32_t)(_ar * A_ROWB + _as * 16), Ah_g + _ag);        \
            cp16(_b + ABYTES + (uint32_t)(_ar * A_ROWB + _as * 16), Al_g + _ag); \
            const int _br = _id >> 4, _bs = _id & 15;                          \
            const size_t _bg = (size_t)(_k0 + _br) * N + bn + _bs * 8;         \
            cp16(_b + 2 * ABYTES + (uint32_t)(_br * B_ROWB + _bs * 16), Bh_g + _bg); \
            cp16(_b + 2 * ABYTES + BBYTES + (uint32_t)(_br * B_ROWB + _bs * 16), Bl_g + _bg); \
        }                                                                      \
    } while (0)

    PJ_FILL(0);
    asm volatile("cp.async.commit_group;");
    if (nst > 1) PJ_FILL(1);
    asm volatile("cp.async.commit_group;");

    for (int st = 0; st < nst; st++) {
        asm volatile("cp.async.wait_group 1;");
        __syncthreads();
        if (st + 2 < nst) PJ_FILL(st + 2);
        asm volatile("cp.async.commit_group;");

        const uint32_t aho = smb + (uint32_t)(st % 3) * BUFB;
        const uint32_t bho = aho + 2 * ABYTES;

        #pragma unroll
        for (int kc = 0; kc < 2; kc++) {
            uint32_t bhf[4][2], blf[4][2];
            #pragma unroll
            for (int fn = 0; fn < 4; fn++) {
                const uint32_t addr = bho + kc * 16 * B_ROWB + b_lane + (uint32_t)(wn * 64 + fn * 16);
                asm volatile("ldmatrix.sync.aligned.m8n8.x2.trans.shared.b16 {%0,%1},[%2];"
                             : "=r"(bhf[fn][0]), "=r"(bhf[fn][1]) : "r"(addr));
                asm volatile("ldmatrix.sync.aligned.m8n8.x2.trans.shared.b16 {%0,%1},[%2];"
                             : "=r"(blf[fn][0]), "=r"(blf[fn][1]) : "r"(addr + BBYTES));
            }
            #pragma unroll
            for (int fm = 0; fm < 4; fm++) {
                const uint32_t aaddr = aho + (uint32_t)((wm * 64 + fm * 16) * A_ROWB) + kc * 32 + a_lane;
                uint32_t ah[4], al[4];
                asm volatile("ldmatrix.sync.aligned.m8n8.x4.shared.b16 {%0,%1,%2,%3},[%4];"
                             : "=r"(ah[0]), "=r"(ah[1]), "=r"(ah[2]), "=r"(ah[3]) : "r"(aaddr));
                asm volatile("ldmatrix.sync.aligned.m8n8.x4.shared.b16 {%0,%1,%2,%3},[%4];"
                             : "=r"(al[0]), "=r"(al[1]), "=r"(al[2]), "=r"(al[3]) : "r"(aaddr + ABYTES));
                #pragma unroll
                for (int fn = 0; fn < 4; fn++) {
                    float* d = acc[fm][fn];
                    asm volatile(
                        "mma.sync.aligned.m16n8k16.row.col.f32.bf16.bf16.f32 "
                        "{%0,%1,%2,%3},{%4,%5,%6,%7},{%8,%9},{%0,%1,%2,%3};\n"
                        : "+f"(d[0]), "+f"(d[1]), "+f"(d[2]), "+f"(d[3])
                        : "r"(ah[0]), "r"(ah[1]), "r"(ah[2]), "r"(ah[3]),
                          "r"(bhf[fn][0]), "r"(bhf[fn][1]));
                    asm volatile(
                        "mma.sync.aligned.m16n8k16.row.col.f32.bf16.bf16.f32 "
                        "{%0,%1,%2,%3},{%4,%5,%6,%7},{%8,%9},{%0,%1,%2,%3};\n"
                        : "+f"(d[0]), "+f"(d[1]), "+f"(d[2]), "+f"(d[3])
                        : "r"(ah[0]), "r"(ah[1]), "r"(ah[2]), "r"(ah[3]),
                          "r"(blf[fn][0]), "r"(blf[fn][1]));
                    asm volatile(
                        "mma.sync.aligned.m16n8k16.row.col.f32.bf16.bf16.f32 "
                        "{%0,%1,%2,%3},{%4,%5,%6,%7},{%8,%9},{%0,%1,%2,%3};\n"
                        : "+f"(d[0]), "+f"(d[1]), "+f"(d[2]), "+f"(d[3])
                        : "r"(al[0]), "r"(al[1]), "r"(al[2]), "r"(al[3]),
                          "r"(bhf[fn][0]), "r"(bhf[fn][1]));
                }
            }
        }
        __syncthreads();
    }
#undef PJ_FILL

    #pragma unroll
    for (int fm = 0; fm < 4; fm++) {
        const int r1 = wm * 64 + fm * 16 + grp;
        const int r2 = r1 + 8;
        const float b1v = bias[bm + r1];
        const float b2v = bias[bm + r2];
        #pragma unroll
        for (int fn = 0; fn < 4; fn++) {
            const int c = wn * 32 + fn * 8 + tig * 2;
            const float* d = acc[fm][fn];
            float2 rr1 = *(const float2*)(resid + (size_t)(bm + r1) * N + bn + c);
            float2 rr2 = *(const float2*)(resid + (size_t)(bm + r2) * N + bn + c);
            float2 o1 = make_float2(d[0] + b1v + rr1.x, d[1] + b1v + rr1.y);
            float2 o2 = make_float2(d[2] + b2v + rr2.x, d[3] + b2v + rr2.y);
            *(float2*)(C + (size_t)(bm + r1) * N + bn + c) = o1;
            *(float2*)(C + (size_t)(bm + r2) * N + bn + c) = o2;
        }
    }
}

// ---------------- bf16-code GEMM (attention GEMMs) ----------------
#define CODE_STAGE 36864
#define SMEM_CODE (3 * CODE_STAGE)

template<int OUT>
__global__ __launch_bounds__(256, 2) void code_gemm_k(
    const __nv_bfloat16* __restrict__ A, const __nv_bfloat16* __restrict__ B,
    __half* __restrict__ C, __nv_bfloat16* __restrict__ Hh, __nv_bfloat16* __restrict__ Hl,
    int M, int N, int K,
    const float* __restrict__ sc1, const float* __restrict__ sc2, float fixed)
{
    extern __shared__ char sm[];
    const uint32_t smb = smem_u32(sm);

    const int bm = blockIdx.y * 128;
    const int bn = blockIdx.x * 128;
    const int tid = threadIdx.x;
    const int w = tid >> 5, lane = tid & 31;
    const int wm = w >> 2, wn = w & 3;
    const int grp = lane >> 2, tig = lane & 3;

    float acc[4][4][4];
    #pragma unroll
    for (int a = 0; a < 4; a++)
        #pragma unroll
        for (int b = 0; b < 4; b++)
            #pragma unroll
            for (int c = 0; c < 4; c++) acc[a][b][c] = 0.f;

    const int nstage = K >> 6;

    const uint32_t a_lm = (uint32_t)((lane & 15) * 144 + (lane >> 4) * 16);
    const uint32_t b_lm = (uint32_t)((lane & 7) * 144 + ((lane >> 3) & 1) * 16);

#define CODE_FILL(ST) do {                                                    \
        const uint32_t _b = smb + (uint32_t)((ST) % 3) * CODE_STAGE;          \
        const int _k0 = (ST) << 6;                                            \
        _Pragma("unroll")                                                     \
        for (int _j = 0; _j < 4; _j++) {                                      \
            const int _id = tid + 256 * _j;                                   \
            const int _r = _id >> 3, _sg = _id & 7;                           \
            cp16(_b + (uint32_t)(_r * 144 + _sg * 16),                        \
                 A + (size_t)(bm + _r) * K + _k0 + _sg * 8);                  \
            cp16(_b + 18432u + (uint32_t)(_r * 144 + _sg * 16),               \
                 B + (size_t)(bn + _r) * K + _k0 + _sg * 8);                  \
        }                                                                     \
    } while (0)

    CODE_FILL(0);
    asm volatile("cp.async.commit_group;");
    if (nstage > 1) CODE_FILL(1);
    asm volatile("cp.async.commit_group;");

    for (int st = 0; st < nstage; st++) {
        asm volatile("cp.async.wait_group 1;");
        __syncthreads();
        if (st + 2 < nstage) CODE_FILL(st + 2);
        asm volatile("cp.async.commit_group;");

        const uint32_t abase = smb + (uint32_t)(st % 3) * CODE_STAGE;
        const uint32_t bbase = abase + 18432u;
        #pragma unroll
        for (int kc = 0; kc < 4; kc++) {
            uint32_t af[4][4], bf[4][2];
            #pragma unroll
            for (int fm = 0; fm < 4; fm++) {
                const uint32_t addr = abase + (uint32_t)((wm * 64 + fm * 16) * 144) + kc * 32 + a_lm;
                asm volatile("ldmatrix.sync.aligned.m8n8.x4.shared.b16 {%0,%1,%2,%3},[%4];"
                             : "=r"(af[fm][0]), "=r"(af[fm][1]), "=r"(af[fm][2]), "=r"(af[fm][3])
                             : "r"(addr));
            }
            #pragma unroll
            for (int fn = 0; fn < 4; fn++) {
                const uint32_t addr = bbase + (uint32_t)((wn * 32 + fn * 8) * 144) + kc * 32 + b_lm;
                asm volatile("ldmatrix.sync.aligned.m8n8.x2.shared.b16 {%0,%1},[%2];"
                             : "=r"(bf[fn][0]), "=r"(bf[fn][1]) : "r"(addr));
            }
            #pragma unroll
            for (int fm = 0; fm < 4; fm++)
                #pragma unroll
                for (int fn = 0; fn < 4; fn++) {
                    float* d = acc[fm][fn];
                    asm volatile(
                        "mma.sync.aligned.m16n8k16.row.col.f32.bf16.bf16.f32 "
                        "{%0,%1,%2,%3},{%4,%5,%6,%7},{%8,%9},{%0,%1,%2,%3};\n"
                        : "+f"(d[0]), "+f"(d[1]), "+f"(d[2]), "+f"(d[3])
                        : "r"(af[fm][0]), "r"(af[fm][1]), "r"(af[fm][2]), "r"(af[fm][3]),
                          "r"(bf[fn][0]), "r"(bf[fn][1]));
                }
        }
        __syncthreads();
    }
#undef CODE_FILL

    const float scale = (*sc1) * (*sc2) * fixed;
    #pragma unroll
    for (int fm = 0; fm < 4; fm++) {
        const int row = bm + wm * 64 + fm * 16 + grp;
        #pragma unroll
        for (int fn = 0; fn < 4; fn++) {
            const int col = bn + wn * 32 + fn * 8 + tig * 2;
            const float* d = acc[fm][fn];
            if (OUT == 0) {
                __half2 v0 = __floats2half2_rn(d[0] * scale, d[1] * scale);
                __half2 v1 = __floats2half2_rn(d[2] * scale, d[3] * scale);
                *(__half2*)(C + (size_t)row * N + col) = v0;
                *(__half2*)(C + (size_t)(row + 8) * N + col) = v1;
            } else {
                uint32_t h01, l01, h23, l23;
                split_pack2(d[0] * scale, d[1] * scale, h01, l01);
                split_pack2(d[2] * scale, d[3] * scale, h23, l23);
                *(uint32_t*)(Hh + (size_t)row * N + col) = h01;
                *(uint32_t*)(Hl + (size_t)row * N + col) = l01;
                *(uint32_t*)(Hh + (size_t)(row + 8) * N + col) = h23;
                *(uint32_t*)(Hl + (size_t)(row + 8) * N + col) = l23;
            }
        }
    }
}

// ---------------- softmax (f16 in) + quant -> bf16 codes ----------------
__global__ __launch_bounds__(256) void softmax_quant_k(
    const __half* __restrict__ S, __nv_bfloat16* __restrict__ Wc,
    const float* __restrict__ d_dw)
{
    const size_t rowoff = (size_t)blockIdx.x * HW;
    const uint4* __restrict__ r8 = (const uint4*)(S + rowoff);
    const int tid = threadIdx.x;

    float v[16];
    #pragma unroll
    for (int u = 0; u < 2; u++) {
        uint4 t = r8[tid + 256 * u];
        const uint32_t* p = (const uint32_t*)&t;
        #pragma unroll
        for (int e = 0; e < 4; e++) {
            float2 f = __half22float2(*(const __half2*)&p[e]);
            v[u * 8 + e * 2]     = f.x;
            v[u * 8 + e * 2 + 1] = f.y;
        }
    }

    float mx = -3.0e38f;
    #pragma unroll
    for (int i = 0; i < 16; i++) mx = fmaxf(mx, v[i]);

    __shared__ float wr[8];
    __shared__ float bcast;
    for (int o = 16; o; o >>= 1) mx = fmaxf(mx, __shfl_xor_sync(0xffffffffu, mx, o));
    const int warp = tid >> 5, lane = tid & 31;
    if (lane == 0) wr[warp] = mx;
    __syncthreads();
    if (tid == 0) {
        float m = wr[0];
        #pragma unroll
        for (int i = 1; i < 8; i++) m = fmaxf(m, wr[i]);
        bcast = m;
    }
    __syncthreads();
    mx = bcast;

    float sum = 0.f;
    #pragma unroll
    for (int i = 0; i < 16; i++) {
        v[i] = __expf(v[i] - mx);
        sum += v[i];
    }
    for (int o = 16; o; o >>= 1) sum += __shfl_xor_sync(0xffffffffu, sum, o);
    __syncthreads();
    if (lane == 0) wr[warp] = sum;
    __syncthreads();
    if (tid == 0) {
        float t = 0.f;
        #pragma unroll
        for (int i = 0; i < 8; i++) t += wr[i];
        bcast = t;
    }
    __syncthreads();
    const float inv = 1.0f / bcast;
    const float invdw = 1.0f / (*d_dw);

    uint2* w2 = (uint2*)(Wc + rowoff);
    #pragma unroll
    for (int u = 0; u < 4; u++) {
        const float* p = v + u * 4;
        float q0 = fminf(fmaxf(rintf(p[0] * inv * invdw), 0.f), 255.f);
        float q1 = fminf(fmaxf(rintf(p[1] * inv * invdw), 0.f), 255.f);
        float q2 = fminf(fmaxf(rintf(p[2] * inv * invdw), 0.f), 255.f);
        float q3 = fminf(fmaxf(rintf(p[3] * inv * invdw), 0.f), 255.f);
        w2[(tid + 256 * (u >> 1)) * 2 + (u & 1)] = make_uint2(bf16pair(q0, q1), bf16pair(q2, q3));
    }
}

// ---------------- launch ----------------
extern "C" void kernel_launch(void* const* d_in, const int* in_sizes, int n_in,
                              void* d_out, int out_size)
{
    const float* x     = (const float*)d_in[0];
    const float* gamma = (const float*)d_in[1];
    const float* beta  = (const float*)d_in[2];
    const float* wsrc[4] = { (const float*)d_in[3], (const float*)d_in[5],
                             (const float*)d_in[7], (const float*)d_in[9] };
    const float* bq    = (const float*)d_in[4];
    const float* bk    = (const float*)d_in[6];
    const float* bv    = (const float*)d_in[8];
    const float* bp    = (const float*)d_in[10];
    const float* dq    = (const float*)d_in[11];
    const float* zq    = (const float*)d_in[12];
    const float* dk    = (const float*)d_in[13];
    const float* zk    = (const float*)d_in[14];
    const float* dv    = (const float*)d_in[15];
    const float* zv    = (const float*)d_in[16];
    const float* dw    = (const float*)d_in[17];
    float* out = (float*)d_out;

    __half* s;
    __nv_bfloat16 *hnh, *hnl, *hh, *hl, *qc, *kc, *vc, *wc, *wh, *wl;
    cudaGetSymbolAddress((void**)&s,   g_s);
    cudaGetSymbolAddress((void**)&hnh, g_hnh);
    cudaGetSymbolAddress((void**)&hnl, g_hnl);
    cudaGetSymbolAddress((void**)&hh,  g_hh);
    cudaGetSymbolAddress((void**)&hl,  g_hl);
    cudaGetSymbolAddress((void**)&qc,  g_qc);
    cudaGetSymbolAddress((void**)&kc,  g_kc);
    cudaGetSymbolAddress((void**)&vc,  g_vc);
    cudaGetSymbolAddress((void**)&wc,  g_wc);
    cudaGetSymbolAddress((void**)&wh,  g_wh);
    cudaGetSymbolAddress((void**)&wl,  g_wl);

    cudaFuncSetAttribute(qkv_gemm_k,  cudaFuncAttributeMaxDynamicSharedMemorySize, SMEM_BF16);
    cudaFuncSetAttribute(proj_gemm_k, cudaFuncAttributeMaxDynamicSharedMemorySize, SMEM_BF16);
    cudaFuncSetAttribute(code_gemm_k<0>, cudaFuncAttributeMaxDynamicSharedMemorySize, SMEM_CODE);
    cudaFuncSetAttribute(code_gemm_k<1>, cudaFuncAttributeMaxDynamicSharedMemorySize, SMEM_CODE);

    const size_t CS = (size_t)CC * HW;
    const size_t PS = (size_t)HW * CC;
    const size_t SS = (size_t)HW * HW;
    const int WN = CC * CC;

    cudaEventRecord(g_sp.evFork, 0);

    // weight splits: wq,wk,wv into contiguous stacked slots 0..2, wp into slot 3
    for (int i = 0; i < 4; i++) {
        cudaStreamWaitEvent(g_sp.s[i], g_sp.evFork, 0);
        wsplit_k<<<WN / 1024, 256, 0, g_sp.s[i]>>>(wsrc[i], wh + (size_t)i * WN, wl + (size_t)i * WN, WN);
        cudaEventRecord(g_sp.evW[i], g_sp.s[i]);
    }

    gn_kernel<<<BB * GROUPS, 256>>>(x, gamma, beta, hnh, hnl);
    cudaEventRecord(g_sp.evGN, 0);

    dim3 gqkv(HW / 128, 12, 1);            // fused q,k,v: 384 CTAs
    dim3 gq1(HW / 128, CC / 128, 1);
    dim3 gs1(HW / 128, HW / 128, 1);

    const __nv_bfloat16* wph = wh + 3 * (size_t)WN;
    const __nv_bfloat16* wpl = wl + 3 * (size_t)WN;

    for (int b = 0; b < BB; b++) {
        cudaStream_t st = g_sp.s[b];
        cudaStreamWaitEvent(st, g_sp.evGN, 0);
        for (int i = 0; i < 4; i++) cudaStreamWaitEvent(st, g_sp.evW[i], 0);

        const __nv_bfloat16* hnh_b = hnh + (size_t)b * CS;
        const __nv_bfloat16* hnl_b = hnl + (size_t)b * CS;
        __nv_bfloat16* qc_b = qc + (size_t)b * PS;
        __nv_bfloat16* kc_b = kc + (size_t)b * PS;
        __nv_bfloat16* vc_b = vc + (size_t)b * CS;
        __half* s_b = s + (size_t)b * SS;
        __nv_bfloat16* wc_b = wc + (size_t)b * SS;
        __nv_bfloat16* hh_b = hh + (size_t)b * CS;
        __nv_bfloat16* hl_b = hl + (size_t)b * CS;

        // fused q/k/v projections (one 384-CTA launch)
        qkv_gemm_k<<<gqkv, 256, SMEM_BF16, st>>>(wh, wl, hnh_b, hnl_b,
            qc_b, kc_b, vc_b, bq, bk, bv, dq, zq, dk, zk, dv, zv);

        code_gemm_k<0><<<gs1, 256, SMEM_CODE, st>>>(qc_b, kc_b, s_b, nullptr, nullptr,
            HW, HW, CC, dq, dk, 0.044194173824159216f);

        softmax_quant_k<<<HW, 256, 0, st>>>(s_b, wc_b, dw);

        code_gemm_k<1><<<gq1, 256, SMEM_CODE, st>>>(vc_b, wc_b, nullptr, hh_b, hl_b,
            CC, HW, HW, dv, dw, 1.0f);

        proj_gemm_k<<<gq1, 256, SMEM_BF16, st>>>(wph, wpl, hh_b, hl_b,
            out + (size_t)b * CS, CC, HW, CC, bp, x + (size_t)b * CS);

        cudaEventRecord(g_sp.evJoin[b], st);
        cudaStreamWaitEvent(0, g_sp.evJoin[b], 0);
    }
}

// round 16
// speedup vs baseline: 1.0093x; 1.0093x over previous
#include <cuda_runtime.h>
#include <cuda_bf16.h>
#include <cuda_fp16.h>
#include <stdint.h>
#include <math.h>

#define BB 4
#define CC 512
#define HW 4096
#define GROUPS 32
#define GSIZE 16

// ---------------- scratch ----------------
__device__ __half        g_s [(size_t)BB * HW * HW];
__device__ __nv_bfloat16 g_hnh[(size_t)BB * CC * HW];
__device__ __nv_bfloat16 g_hnl[(size_t)BB * CC * HW];
__device__ __nv_bfloat16 g_hh[(size_t)BB * CC * HW];
__device__ __nv_bfloat16 g_hl[(size_t)BB * CC * HW];
__device__ __nv_bfloat16 g_qc[(size_t)BB * HW * CC];
__device__ __nv_bfloat16 g_kc[(size_t)BB * HW * CC];
__device__ __nv_bfloat16 g_vc[(size_t)BB * CC * HW];
__device__ __nv_bfloat16 g_wc[(size_t)BB * HW * HW];
__device__ __nv_bfloat16 g_wh[4][CC * CC];   // wq,wk,wv stacked (rows 0..1535), wp
__device__ __nv_bfloat16 g_wl[4][CC * CC];

// ---------------- streams/events ----------------
struct StreamPack {
    cudaStream_t s[4];
    cudaEvent_t evFork, evW[4], evJoin[4];
    StreamPack() {
        for (int i = 0; i < 4; i++) cudaStreamCreateWithFlags(&s[i], cudaStreamNonBlocking);
        cudaEventCreateWithFlags(&evFork, cudaEventDisableTiming);
        for (int i = 0; i < 4; i++) cudaEventCreateWithFlags(&evW[i], cudaEventDisableTiming);
        for (int i = 0; i < 4; i++) cudaEventCreateWithFlags(&evJoin[i], cudaEventDisableTiming);
    }
};
static StreamPack g_sp;

__device__ __forceinline__ uint32_t smem_u32(const void* p) {
    return (uint32_t)__cvta_generic_to_shared(p);
}
__device__ __forceinline__ void cp16(uint32_t dst, const void* src) {
    asm volatile("cp.async.cg.shared.global [%0], [%1], 16;" :: "r"(dst), "l"(src));
}
__device__ __forceinline__ uint32_t bf16pair(float a, float b) {
    return (uint32_t)__bfloat16_as_ushort(__float2bfloat16(a)) |
           ((uint32_t)__bfloat16_as_ushort(__float2bfloat16(b)) << 16);
}
__device__ __forceinline__ void split_pack2(float a0, float a1, uint32_t& hi, uint32_t& lo) {
    __nv_bfloat16 h0 = __float2bfloat16(a0);
    __nv_bfloat16 h1 = __float2bfloat16(a1);
    __nv_bfloat16 l0 = __float2bfloat16(a0 - __bfloat162float(h0));
    __nv_bfloat16 l1 = __float2bfloat16(a1 - __bfloat162float(h1));
    hi = (uint32_t)__bfloat16_as_ushort(h0) | ((uint32_t)__bfloat16_as_ushort(h1) << 16);
    lo = (uint32_t)__bfloat16_as_ushort(l0) | ((uint32_t)__bfloat16_as_ushort(l1) << 16);
}

// ---------------- weight split ----------------
__global__ __launch_bounds__(256) void wsplit_k(
    const float* __restrict__ src, __nv_bfloat16* __restrict__ hi,
    __nv_bfloat16* __restrict__ lo, int n)
{
    const int i = (blockIdx.x * 256 + threadIdx.x) * 4;
    if (i >= n) return;
    float4 t = *(const float4*)(src + i);
    uint32_t h01, l01, h23, l23;
    split_pack2(t.x, t.y, h01, l01);
    split_pack2(t.z, t.w, h23, l23);
    *(uint2*)(hi + i) = make_uint2(h01, h23);
    *(uint2*)(lo + i) = make_uint2(l01, l23);
}

// ---------------- per-batch GroupNorm -> bf16 hi/lo ----------------
// grid = GROUPS (32), pointers pre-offset per batch.
__global__ __launch_bounds__(256) void gn_kernel(
    const float* __restrict__ x, const float* __restrict__ gamma,
    const float* __restrict__ beta,
    __nv_bfloat16* __restrict__ oh, __nv_bfloat16* __restrict__ ol)
{
    const int g = blockIdx.x;
    const size_t base = (size_t)g * GSIZE * HW;
    const int LEN4 = (GSIZE * HW) / 4;
    const float4* __restrict__ xin = (const float4*)(x + base);

    float s = 0.f, s2 = 0.f;
    for (int i = threadIdx.x; i < LEN4; i += 256) {
        float4 t = xin[i];
        s  += t.x + t.y + t.z + t.w;
        s2 += t.x * t.x + t.y * t.y + t.z * t.z + t.w * t.w;
    }
    __shared__ float wr1[8], wr2[8];
    __shared__ float s_mu, s_rstd;
    for (int o = 16; o; o >>= 1) {
        s  += __shfl_xor_sync(0xffffffffu, s,  o);
        s2 += __shfl_xor_sync(0xffffffffu, s2, o);
    }
    const int warp = threadIdx.x >> 5, lane = threadIdx.x & 31;
    if (lane == 0) { wr1[warp] = s; wr2[warp] = s2; }
    __syncthreads();
    if (threadIdx.x == 0) {
        float ts = 0.f, ts2 = 0.f;
        #pragma unroll
        for (int i = 0; i < 8; i++) { ts += wr1[i]; ts2 += wr2[i]; }
        const float inv_n = 1.0f / (float)(GSIZE * HW);
        float mu  = ts * inv_n;
        float var = ts2 * inv_n - mu * mu;
        s_mu = mu;
        s_rstd = 1.0f / sqrtf(var + 1e-6f);
    }
    __syncthreads();
    const float mu = s_mu, rstd = s_rstd;

    for (int i = threadIdx.x; i < LEN4; i += 256) {
        float4 t = xin[i];
        const int c = g * GSIZE + ((i * 4) >> 12);
        const float ga = gamma[c] * rstd, be = beta[c];
        t.x = (t.x - mu) * ga + be;
        t.y = (t.y - mu) * ga + be;
        t.z = (t.z - mu) * ga + be;
        t.w = (t.w - mu) * ga + be;
        uint32_t h01, l01, h23, l23;
        split_pack2(t.x, t.y, h01, l01);
        split_pack2(t.z, t.w, h23, l23);
        *(uint2*)(oh + base + (size_t)i * 4) = make_uint2(h01, h23);
        *(uint2*)(ol + base + (size_t)i * 4) = make_uint2(l01, l23);
    }
}

// ---------------- common bf16x3 mainloop pieces ----------------
#define A_ROWB 80
#define B_ROWB 272
#define ABYTES (128 * A_ROWB)
#define BBYTES (32 * B_ROWB)
#define BUFB   (2 * ABYTES + 2 * BBYTES)
#define SMEM_BF16 (3 * BUFB)

// ---------------- QKV projection GEMM (stacked weights, byoff selects slice) ----------------
// grid = (HW/128, NY). effective by = blockIdx.y + byoff; p = by>>2 (0=q,1=k,2=v).
__global__ __launch_bounds__(256, 2) void qkv_gemm_k(
    const __nv_bfloat16* __restrict__ Ah_g, const __nv_bfloat16* __restrict__ Al_g,
    const __nv_bfloat16* __restrict__ Bh_g, const __nv_bfloat16* __restrict__ Bl_g,
    __nv_bfloat16* __restrict__ Qc, __nv_bfloat16* __restrict__ Kc, __nv_bfloat16* __restrict__ Vc,
    const float* __restrict__ bq, const float* __restrict__ bk, const float* __restrict__ bv,
    const float* __restrict__ dq, const float* __restrict__ zq,
    const float* __restrict__ dk, const float* __restrict__ zk,
    const float* __restrict__ dv, const float* __restrict__ zv,
    int byoff)
{
    extern __shared__ char sm[];
    const uint32_t smb = smem_u32(sm);

    const int K = CC, N = HW, M = CC;
    const int by = blockIdx.y + byoff;
    const int p = by >> 2;
    const int bm = by * 128;
    const int bmL = (by & 3) * 128;
    const int bn = blockIdx.x * 128;
    const int tid = threadIdx.x;
    const int w = tid >> 5, lane = tid & 31;
    const int wm = w >> 2, wn = w & 3;
    const int grp = lane >> 2, tig = lane & 3;

    float acc[4][4][4];
    #pragma unroll
    for (int a = 0; a < 4; a++)
        #pragma unroll
        for (int b = 0; b < 4; b++)
            #pragma unroll
            for (int c = 0; c < 4; c++) acc[a][b][c] = 0.f;

    const uint32_t a_lane = (uint32_t)(lane & 15) * A_ROWB + (uint32_t)(lane >> 4) * 16;
    const uint32_t b_lane = (uint32_t)(lane & 15) * B_ROWB;

    const int nst = K >> 5;

#define PJ_FILL(ST) do {                                                       \
        const uint32_t _b = smb + (uint32_t)((ST) % 3) * BUFB;                 \
        const int _k0 = (ST) << 5;                                             \
        _Pragma("unroll")                                                      \
        for (int _j = 0; _j < 2; _j++) {                                       \
            const int _id = tid + 256 * _j;                                    \
            const int _ar = _id >> 2, _as = _id & 3;                           \
            const size_t _ag = (size_t)(bm + _ar) * K + _k0 + _as * 8;         \
            cp16(_b + (uint32_t)(_ar * A_ROWB + _as * 16), Ah_g + _ag);        \
            cp16(_b + ABYTES + (uint32_t)(_ar * A_ROWB + _as * 16), Al_g + _ag); \
            const int _br = _id >> 4, _bs = _id & 15;                          \
            const size_t _bg = (size_t)(_k0 + _br) * N + bn + _bs * 8;         \
            cp16(_b + 2 * ABYTES + (uint32_t)(_br * B_ROWB + _bs * 16), Bh_g + _bg); \
            cp16(_b + 2 * ABYTES + BBYTES + (uint32_t)(_br * B_ROWB + _bs * 16), Bl_g + _bg); \
        }                                                                      \
    } while (0)

    PJ_FILL(0);
    asm volatile("cp.async.commit_group;");
    if (nst > 1) PJ_FILL(1);
    asm volatile("cp.async.commit_group;");

    for (int st = 0; st < nst; st++) {
        asm volatile("cp.async.wait_group 1;");
        __syncthreads();
        if (st + 2 < nst) PJ_FILL(st + 2);
        asm volatile("cp.async.commit_group;");

        const uint32_t aho = smb + (uint32_t)(st % 3) * BUFB;
        const uint32_t bho = aho + 2 * ABYTES;

        #pragma unroll
        for (int kc = 0; kc < 2; kc++) {
            uint32_t bhf[4][2], blf[4][2];
            #pragma unroll
            for (int fn = 0; fn < 4; fn++) {
                const uint32_t addr = bho + kc * 16 * B_ROWB + b_lane + (uint32_t)(wn * 64 + fn * 16);
                asm volatile("ldmatrix.sync.aligned.m8n8.x2.trans.shared.b16 {%0,%1},[%2];"
                             : "=r"(bhf[fn][0]), "=r"(bhf[fn][1]) : "r"(addr));
                asm volatile("ldmatrix.sync.aligned.m8n8.x2.trans.shared.b16 {%0,%1},[%2];"
                             : "=r"(blf[fn][0]), "=r"(blf[fn][1]) : "r"(addr + BBYTES));
            }
            #pragma unroll
            for (int fm = 0; fm < 4; fm++) {
                const uint32_t aaddr = aho + (uint32_t)((wm * 64 + fm * 16) * A_ROWB) + kc * 32 + a_lane;
                uint32_t ah[4], al[4];
                asm volatile("ldmatrix.sync.aligned.m8n8.x4.shared.b16 {%0,%1,%2,%3},[%4];"
                             : "=r"(ah[0]), "=r"(ah[1]), "=r"(ah[2]), "=r"(ah[3]) : "r"(aaddr));
                asm volatile("ldmatrix.sync.aligned.m8n8.x4.shared.b16 {%0,%1,%2,%3},[%4];"
                             : "=r"(al[0]), "=r"(al[1]), "=r"(al[2]), "=r"(al[3]) : "r"(aaddr + ABYTES));
                #pragma unroll
                for (int fn = 0; fn < 4; fn++) {
                    float* d = acc[fm][fn];
                    asm volatile(
                        "mma.sync.aligned.m16n8k16.row.col.f32.bf16.bf16.f32 "
                        "{%0,%1,%2,%3},{%4,%5,%6,%7},{%8,%9},{%0,%1,%2,%3};\n"
                        : "+f"(d[0]), "+f"(d[1]), "+f"(d[2]), "+f"(d[3])
                        : "r"(ah[0]), "r"(ah[1]), "r"(ah[2]), "r"(ah[3]),
                          "r"(bhf[fn][0]), "r"(bhf[fn][1]));
                    asm volatile(
                        "mma.sync.aligned.m16n8k16.row.col.f32.bf16.bf16.f32 "
                        "{%0,%1,%2,%3},{%4,%5,%6,%7},{%8,%9},{%0,%1,%2,%3};\n"
                        : "+f"(d[0]), "+f"(d[1]), "+f"(d[2]), "+f"(d[3])
                        : "r"(ah[0]), "r"(ah[1]), "r"(ah[2]), "r"(ah[3]),
                          "r"(blf[fn][0]), "r"(blf[fn][1]));
                    asm volatile(
                        "mma.sync.aligned.m16n8k16.row.col.f32.bf16.bf16.f32 "
                        "{%0,%1,%2,%3},{%4,%5,%6,%7},{%8,%9},{%0,%1,%2,%3};\n"
                        : "+f"(d[0]), "+f"(d[1]), "+f"(d[2]), "+f"(d[3])
                        : "r"(al[0]), "r"(al[1]), "r"(al[2]), "r"(al[3]),
                          "r"(bhf[fn][0]), "r"(bhf[fn][1]));
                }
            }
        }
        __syncthreads();
    }
#undef PJ_FILL

    const float delta = (p == 0) ? *dq : (p == 1) ? *dk : *dv;
    const float zp    = (p == 0) ? *zq : (p == 1) ? *zk : *zv;
    const float* bias = (p == 0) ? bq : (p == 1) ? bk : bv;
    const float invd = 1.0f / delta;

    if (p == 2) {
        __nv_bfloat16* Cb = Vc;
        #pragma unroll
        for (int fm = 0; fm < 4; fm++) {
            const int r1 = wm * 64 + fm * 16 + grp;
            const int r2 = r1 + 8;
            const float b1v = bias[bmL + r1];
            const float b2v = bias[bmL + r2];
            #pragma unroll
            for (int fn = 0; fn < 4; fn++) {
                const int c = wn * 32 + fn * 8 + tig * 2;
                const float* d = acc[fm][fn];
                float q0 = fminf(fmaxf(rintf((d[0] + b1v) * invd) + zp, 0.f), 255.f) - zp;
                float q1 = fminf(fmaxf(rintf((d[1] + b1v) * invd) + zp, 0.f), 255.f) - zp;
                float q2 = fminf(fmaxf(rintf((d[2] + b2v) * invd) + zp, 0.f), 255.f) - zp;
                float q3 = fminf(fmaxf(rintf((d[3] + b2v) * invd) + zp, 0.f), 255.f) - zp;
                *(uint32_t*)(Cb + (size_t)(bmL + r1) * N + bn + c) = bf16pair(q0, q1);
                *(uint32_t*)(Cb + (size_t)(bmL + r2) * N + bn + c) = bf16pair(q2, q3);
            }
        }
    } else {
        __nv_bfloat16* Cb = (p == 0) ? Qc : Kc;
        __nv_bfloat16* t16 = (__nv_bfloat16*)sm;
        #pragma unroll
        for (int fm = 0; fm < 4; fm++) {
            const int r1 = wm * 64 + fm * 16 + grp;
            const int r2 = r1 + 8;
            const float b1v = bias[bmL + r1];
            const float b2v = bias[bmL + r2];
            #pragma unroll
            for (int fn = 0; fn < 4; fn++) {
                const int c = wn * 32 + fn * 8 + tig * 2;
                const float* d = acc[fm][fn];
                float q0 = fminf(fmaxf(rintf((d[0] + b1v) * invd) + zp, 0.f), 255.f) - zp;
                float q1 = fminf(fmaxf(rintf((d[1] + b1v) * invd) + zp, 0.f), 255.f) - zp;
                float q2 = fminf(fmaxf(rintf((d[2] + b2v) * invd) + zp, 0.f), 255.f) - zp;
                float q3 = fminf(fmaxf(rintf((d[3] + b2v) * invd) + zp, 0.f), 255.f) - zp;
                t16[(c + 0) * 136 + r1] = __float2bfloat16(q0);
                t16[(c + 1) * 136 + r1] = __float2bfloat16(q1);
                t16[(c + 0) * 136 + r2] = __float2bfloat16(q2);
                t16[(c + 1) * 136 + r2] = __float2bfloat16(q3);
            }
        }
        __syncthreads();
        #pragma unroll
        for (int it = 0; it < 8; it++) {
            const int l = tid + 256 * it;
            const int row = l >> 4;
            const int seg = l & 15;
            uint4 val = *(uint4*)(t16 + row * 136 + seg * 8);
            *(uint4*)(Cb + (size_t)(bn + row) * M + bmL + seg * 8) = val;
        }
    }
}

// ---------------- output projection GEMM ----------------
__global__ __launch_bounds__(256, 2) void proj_gemm_k(
    const __nv_bfloat16* __restrict__ Ah_g, const __nv_bfloat16* __restrict__ Al_g,
    const __nv_bfloat16* __restrict__ Bh_g, const __nv_bfloat16* __restrict__ Bl_g,
    float* __restrict__ C, int M, int N, int K,
    const float* __restrict__ bias, const float* __restrict__ resid)
{
    extern __shared__ char sm[];
    const uint32_t smb = smem_u32(sm);

    const int bm = blockIdx.y * 128;
    const int bn = blockIdx.x * 128;
    const int tid = threadIdx.x;
    const int w = tid >> 5, lane = tid & 31;
    const int wm = w >> 2, wn = w & 3;
    const int grp = lane >> 2, tig = lane & 3;

    float acc[4][4][4];
    #pragma unroll
    for (int a = 0; a < 4; a++)
        #pragma unroll
        for (int b = 0; b < 4; b++)
            #pragma unroll
            for (int c = 0; c < 4; c++) acc[a][b][c] = 0.f;

    const uint32_t a_lane = (uint32_t)(lane & 15) * A_ROWB + (uint32_t)(lane >> 4) * 16;
    const uint32_t b_lane = (uint32_t)(lane & 15) * B_ROWB;

    const int nst = K >> 5;

#define PJ_FILL(ST) do {                                                       \
        const uint32_t _b = smb + (uint32_t)((ST) % 3) * BUFB;                 \
        const int _k0 = (ST) << 5;                                             \
        _Pragma("unroll")                                                      \
        for (int _j = 0; _j < 2; _j++) {                                       \
            const int _id = tid + 256 * _j;                                    \
            const int _ar = _id >> 2, _as = _id & 3;                           \
            const size_t _ag = (size_t)(bm + _ar) * K + _k0 + _as * 8;         \
            cp16(_b + (uint32_t)(_ar * A_ROWB + _as * 16), Ah_g + _ag);        \
            cp16(_b + ABYTES + (uint32_t)(_ar * A_ROWB + _as * 16), Al_g + _ag); \
            const int _br = _id >> 4, _bs = _id & 15;                          \
            const size_t _bg = (size_t)(_k0 + _br) * N + bn + _bs * 8;         \
            cp16(_b + 2 * ABYTES + (uint32_t)(_br * B_ROWB + _bs * 16), Bh_g + _bg); \
            cp16(_b + 2 * ABYTES + BBYTES + (uint32_t)(_br * B_ROWB + _bs * 16), Bl_g + _bg); \
        }                                                                      \
    } while (0)

    PJ_FILL(0);
    asm volatile("cp.async.commit_group;");
    if (nst > 1) PJ_FILL(1);
    asm volatile("cp.async.commit_group;");

    for (int st = 0; st < nst; st++) {
        asm volatile("cp.async.wait_group 1;");
        __syncthreads();
        if (st + 2 < nst) PJ_FILL(st + 2);
        asm volatile("cp.async.commit_group;");

        const uint32_t aho = smb + (uint32_t)(st % 3) * BUFB;
        const uint32_t bho = aho + 2 * ABYTES;

        #pragma unroll
        for (int kc = 0; kc < 2; kc++) {
            uint32_t bhf[4][2], blf[4][2];
            #pragma unroll
            for (int fn = 0; fn < 4; fn++) {
                const uint32_t addr = bho + kc * 16 * B_ROWB + b_lane + (uint32_t)(wn * 64 + fn * 16);
                asm volatile("ldmatrix.sync.aligned.m8n8.x2.trans.shared.b16 {%0,%1},[%2];"
                             : "=r"(bhf[fn][0]), "=r"(bhf[fn][1]) : "r"(addr));
                asm volatile("ldmatrix.sync.aligned.m8n8.x2.trans.shared.b16 {%0,%1},[%2];"
                             : "=r"(blf[fn][0]), "=r"(blf[fn][1]) : "r"(addr + BBYTES));
            }
            #pragma unroll
            for (int fm = 0; fm < 4; fm++) {
                const uint32_t aaddr = aho + (uint32_t)((wm * 64 + fm * 16) * A_ROWB) + kc * 32 + a_lane;
                uint32_t ah[4], al[4];
                asm volatile("ldmatrix.sync.aligned.m8n8.x4.shared.b16 {%0,%1,%2,%3},[%4];"
                             : "=r"(ah[0]), "=r"(ah[1]), "=r"(ah[2]), "=r"(ah[3]) : "r"(aaddr));
                asm volatile("ldmatrix.sync.aligned.m8n8.x4.shared.b16 {%0,%1,%2,%3},[%4];"
                             : "=r"(al[0]), "=r"(al[1]), "=r"(al[2]), "=r"(al[3]) : "r"(aaddr + ABYTES));
                #pragma unroll
                for (int fn = 0; fn < 4; fn++) {
                    float* d = acc[fm][fn];
                    asm volatile(
                        "mma.sync.aligned.m16n8k16.row.col.f32.bf16.bf16.f32 "
                        "{%0,%1,%2,%3},{%4,%5,%6,%7},{%8,%9},{%0,%1,%2,%3};\n"
                        : "+f"(d[0]), "+f"(d[1]), "+f"(d[2]), "+f"(d[3])
                        : "r"(ah[0]), "r"(ah[1]), "r"(ah[2]), "r"(ah[3]),
                          "r"(bhf[fn][0]), "r"(bhf[fn][1]));
                    asm volatile(
                        "mma.sync.aligned.m16n8k16.row.col.f32.bf16.bf16.f32 "
                        "{%0,%1,%2,%3},{%4,%5,%6,%7},{%8,%9},{%0,%1,%2,%3};\n"
                        : "+f"(d[0]), "+f"(d[1]), "+f"(d[2]), "+f"(d[3])
                        : "r"(ah[0]), "r"(ah[1]), "r"(ah[2]), "r"(ah[3]),
                          "r"(blf[fn][0]), "r"(blf[fn][1]));
                    asm volatile(
                        "mma.sync.aligned.m16n8k16.row.col.f32.bf16.bf16.f32 "
                        "{%0,%1,%2,%3},{%4,%5,%6,%7},{%8,%9},{%0,%1,%2,%3};\n"
                        : "+f"(d[0]), "+f"(d[1]), "+f"(d[2]), "+f"(d[3])
                        : "r"(al[0]), "r"(al[1]), "r"(al[2]), "r"(al[3]),
                          "r"(bhf[fn][0]), "r"(bhf[fn][1]));
                }
            }
        }
        __syncthreads();
    }
#undef PJ_FILL

    #pragma unroll
    for (int fm = 0; fm < 4; fm++) {
        const int r1 = wm * 64 + fm * 16 + grp;
        const int r2 = r1 + 8;
        const float b1v = bias[bm + r1];
        const float b2v = bias[bm + r2];
        #pragma unroll
        for (int fn = 0; fn < 4; fn++) {
            const int c = wn * 32 + fn * 8 + tig * 2;
            const float* d = acc[fm][fn];
            float2 rr1 = *(const float2*)(resid + (size_t)(bm + r1) * N + bn + c);
            float2 rr2 = *(const float2*)(resid + (size_t)(bm + r2) * N + bn + c);
            float2 o1 = make_float2(d[0] + b1v + rr1.x, d[1] + b1v + rr1.y);
            float2 o2 = make_float2(d[2] + b2v + rr2.x, d[3] + b2v + rr2.y);
            *(float2*)(C + (size_t)(bm + r1) * N + bn + c) = o1;
            *(float2*)(C + (size_t)(bm + r2) * N + bn + c) = o2;
        }
    }
}

// ---------------- bf16-code GEMM (attention GEMMs) ----------------
#define CODE_STAGE 36864
#define SMEM_CODE (3 * CODE_STAGE)

template<int OUT>
__global__ __launch_bounds__(256, 2) void code_gemm_k(
    const __nv_bfloat16* __restrict__ A, const __nv_bfloat16* __restrict__ B,
    __half* __restrict__ C, __nv_bfloat16* __restrict__ Hh, __nv_bfloat16* __restrict__ Hl,
    int M, int N, int K,
    const float* __restrict__ sc1, const float* __restrict__ sc2, float fixed)
{
    extern __shared__ char sm[];
    const uint32_t smb = smem_u32(sm);

    const int bm = blockIdx.y * 128;
    const int bn = blockIdx.x * 128;
    const int tid = threadIdx.x;
    const int w = tid >> 5, lane = tid & 31;
    const int wm = w >> 2, wn = w & 3;
    const int grp = lane >> 2, tig = lane & 3;

    float acc[4][4][4];
    #pragma unroll
    for (int a = 0; a < 4; a++)
        #pragma unroll
        for (int b = 0; b < 4; b++)
            #pragma unroll
            for (int c = 0; c < 4; c++) acc[a][b][c] = 0.f;

    const int nstage = K >> 6;

    const uint32_t a_lm = (uint32_t)((lane & 15) * 144 + (lane >> 4) * 16);
    const uint32_t b_lm = (uint32_t)((lane & 7) * 144 + ((lane >> 3) & 1) * 16);

#define CODE_FILL(ST) do {                                                    \
        const uint32_t _b = smb + (uint32_t)((ST) % 3) * CODE_STAGE;          \
        const int _k0 = (ST) << 6;                                            \
        _Pragma("unroll")                                                     \
        for (int _j = 0; _j < 4; _j++) {                                      \
            const int _id = tid + 256 * _j;                                   \
            const int _r = _id >> 3, _sg = _id & 7;                           \
            cp16(_b + (uint32_t)(_r * 144 + _sg * 16),                        \
                 A + (size_t)(bm + _r) * K + _k0 + _sg * 8);                  \
            cp16(_b + 18432u + (uint32_t)(_r * 144 + _sg * 16),               \
                 B + (size_t)(bn + _r) * K + _k0 + _sg * 8);                  \
        }                                                                     \
    } while (0)

    CODE_FILL(0);
    asm volatile("cp.async.commit_group;");
    if (nstage > 1) CODE_FILL(1);
    asm volatile("cp.async.commit_group;");

    for (int st = 0; st < nstage; st++) {
        asm volatile("cp.async.wait_group 1;");
        __syncthreads();
        if (st + 2 < nstage) CODE_FILL(st + 2);
        asm volatile("cp.async.commit_group;");

        const uint32_t abase = smb + (uint32_t)(st % 3) * CODE_STAGE;
        const uint32_t bbase = abase + 18432u;
        #pragma unroll
        for (int kc = 0; kc < 4; kc++) {
            uint32_t af[4][4], bf[4][2];
            #pragma unroll
            for (int fm = 0; fm < 4; fm++) {
                const uint32_t addr = abase + (uint32_t)((wm * 64 + fm * 16) * 144) + kc * 32 + a_lm;
                asm volatile("ldmatrix.sync.aligned.m8n8.x4.shared.b16 {%0,%1,%2,%3},[%4];"
                             : "=r"(af[fm][0]), "=r"(af[fm][1]), "=r"(af[fm][2]), "=r"(af[fm][3])
                             : "r"(addr));
            }
            #pragma unroll
            for (int fn = 0; fn < 4; fn++) {
                const uint32_t addr = bbase + (uint32_t)((wn * 32 + fn * 8) * 144) + kc * 32 + b_lm;
                asm volatile("ldmatrix.sync.aligned.m8n8.x2.shared.b16 {%0,%1},[%2];"
                             : "=r"(bf[fn][0]), "=r"(bf[fn][1]) : "r"(addr));
            }
            #pragma unroll
            for (int fm = 0; fm < 4; fm++)
                #pragma unroll
                for (int fn = 0; fn < 4; fn++) {
                    float* d = acc[fm][fn];
                    asm volatile(
                        "mma.sync.aligned.m16n8k16.row.col.f32.bf16.bf16.f32 "
                        "{%0,%1,%2,%3},{%4,%5,%6,%7},{%8,%9},{%0,%1,%2,%3};\n"
                        : "+f"(d[0]), "+f"(d[1]), "+f"(d[2]), "+f"(d[3])
                        : "r"(af[fm][0]), "r"(af[fm][1]), "r"(af[fm][2]), "r"(af[fm][3]),
                          "r"(bf[fn][0]), "r"(bf[fn][1]));
                }
        }
        __syncthreads();
    }
#undef CODE_FILL

    const float scale = (*sc1) * (*sc2) * fixed;
    #pragma unroll
    for (int fm = 0; fm < 4; fm++) {
        const int row = bm + wm * 64 + fm * 16 + grp;
        #pragma unroll
        for (int fn = 0; fn < 4; fn++) {
            const int col = bn + wn * 32 + fn * 8 + tig * 2;
            const float* d = acc[fm][fn];
            if (OUT == 0) {
                __half2 v0 = __floats2half2_rn(d[0] * scale, d[1] * scale);
                __half2 v1 = __floats2half2_rn(d[2] * scale, d[3] * scale);
                *(__half2*)(C + (size_t)row * N + col) = v0;
                *(__half2*)(C + (size_t)(row + 8) * N + col) = v1;
            } else {
                uint32_t h01, l01, h23, l23;
                split_pack2(d[0] * scale, d[1] * scale, h01, l01);
                split_pack2(d[2] * scale, d[3] * scale, h23, l23);
                *(uint32_t*)(Hh + (size_t)row * N + col) = h01;
                *(uint32_t*)(Hl + (size_t)row * N + col) = l01;
                *(uint32_t*)(Hh + (size_t)(row + 8) * N + col) = h23;
                *(uint32_t*)(Hl + (size_t)(row + 8) * N + col) = l23;
            }
        }
    }
}

// ---------------- softmax (f16 in) + quant -> bf16 codes ----------------
__global__ __launch_bounds__(256) void softmax_quant_k(
    const __half* __restrict__ S, __nv_bfloat16* __restrict__ Wc,
    const float* __restrict__ d_dw)
{
    const size_t rowoff = (size_t)blockIdx.x * HW;
    const uint4* __restrict__ r8 = (const uint4*)(S + rowoff);
    const int tid = threadIdx.x;

    float v[16];
    #pragma unroll
    for (int u = 0; u < 2; u++) {
        uint4 t = r8[tid + 256 * u];
        const uint32_t* p = (const uint32_t*)&t;
        #pragma unroll
        for (int e = 0; e < 4; e++) {
            float2 f = __half22float2(*(const __half2*)&p[e]);
            v[u * 8 + e * 2]     = f.x;
            v[u * 8 + e * 2 + 1] = f.y;
        }
    }

    float mx = -3.0e38f;
    #pragma unroll
    for (int i = 0; i < 16; i++) mx = fmaxf(mx, v[i]);

    __shared__ float wr[8];
    __shared__ float bcast;
    for (int o = 16; o; o >>= 1) mx = fmaxf(mx, __shfl_xor_sync(0xffffffffu, mx, o));
    const int warp = tid >> 5, lane = tid & 31;
    if (lane == 0) wr[warp] = mx;
    __syncthreads();
    if (tid == 0) {
        float m = wr[0];
        #pragma unroll
        for (int i = 1; i < 8; i++) m = fmaxf(m, wr[i]);
        bcast = m;
    }
    __syncthreads();
    mx = bcast;

    float sum = 0.f;
    #pragma unroll
    for (int i = 0; i < 16; i++) {
        v[i] = __expf(v[i] - mx);
        sum += v[i];
    }
    for (int o = 16; o; o >>= 1) sum += __shfl_xor_sync(0xffffffffu, sum, o);
    __syncthreads();
    if (lane == 0) wr[warp] = sum;
    __syncthreads();
    if (tid == 0) {
        float t = 0.f;
        #pragma unroll
        for (int i = 0; i < 8; i++) t += wr[i];
        bcast = t;
    }
    __syncthreads();
    const float inv = 1.0f / bcast;
    const float invdw = 1.0f / (*d_dw);

    uint2* w2 = (uint2*)(Wc + rowoff);
    #pragma unroll
    for (int u = 0; u < 4; u++) {
        const float* p = v + u * 4;
        float q0 = fminf(fmaxf(rintf(p[0] * inv * invdw), 0.f), 255.f);
        float q1 = fminf(fmaxf(rintf(p[1] * inv * invdw), 0.f), 255.f);
        float q2 = fminf(fmaxf(rintf(p[2] * inv * invdw), 0.f), 255.f);
        float q3 = fminf(fmaxf(rintf(p[3] * inv * invdw), 0.f), 255.f);
        w2[(tid + 256 * (u >> 1)) * 2 + (u & 1)] = make_uint2(bf16pair(q0, q1), bf16pair(q2, q3));
    }
}

// ---------------- launch ----------------
extern "C" void kernel_launch(void* const* d_in, const int* in_sizes, int n_in,
                              void* d_out, int out_size)
{
    const float* x     = (const float*)d_in[0];
    const float* gamma = (const float*)d_in[1];
    const float* beta  = (const float*)d_in[2];
    const float* wsrc[4] = { (const float*)d_in[3], (const float*)d_in[5],
                             (const float*)d_in[7], (const float*)d_in[9] };
    const float* bq    = (const float*)d_in[4];
    const float* bk    = (const float*)d_in[6];
    const float* bv    = (const float*)d_in[8];
    const float* bp    = (const float*)d_in[10];
    const float* dq    = (const float*)d_in[11];
    const float* zq    = (const float*)d_in[12];
    const float* dk    = (const float*)d_in[13];
    const float* zk    = (const float*)d_in[14];
    const float* dv    = (const float*)d_in[15];
    const float* zv    = (const float*)d_in[16];
    const float* dw    = (const float*)d_in[17];
    float* out = (float*)d_out;

    __half* s;
    __nv_bfloat16 *hnh, *hnl, *hh, *hl, *qc, *kc, *vc, *wc, *wh, *wl;
    cudaGetSymbolAddress((void**)&s,   g_s);
    cudaGetSymbolAddress((void**)&hnh, g_hnh);
    cudaGetSymbolAddress((void**)&hnl, g_hnl);
    cudaGetSymbolAddress((void**)&hh,  g_hh);
    cudaGetSymbolAddress((void**)&hl,  g_hl);
    cudaGetSymbolAddress((void**)&qc,  g_qc);
    cudaGetSymbolAddress((void**)&kc,  g_kc);
    cudaGetSymbolAddress((void**)&vc,  g_vc);
    cudaGetSymbolAddress((void**)&wc,  g_wc);
    cudaGetSymbolAddress((void**)&wh,  g_wh);
    cudaGetSymbolAddress((void**)&wl,  g_wl);

    cudaFuncSetAttribute(qkv_gemm_k,  cudaFuncAttributeMaxDynamicSharedMemorySize, SMEM_BF16);
    cudaFuncSetAttribute(proj_gemm_k, cudaFuncAttributeMaxDynamicSharedMemorySize, SMEM_BF16);
    cudaFuncSetAttribute(code_gemm_k<0>, cudaFuncAttributeMaxDynamicSharedMemorySize, SMEM_CODE);
    cudaFuncSetAttribute(code_gemm_k<1>, cudaFuncAttributeMaxDynamicSharedMemorySize, SMEM_CODE);

    const size_t CS = (size_t)CC * HW;
    const size_t PS = (size_t)HW * CC;
    const size_t SS = (size_t)HW * HW;
    const int WN = CC * CC;

    cudaEventRecord(g_sp.evFork, 0);

    // per-stream: weight split then this batch's GroupNorm (overlapped)
    for (int i = 0; i < 4; i++) {
        cudaStreamWaitEvent(g_sp.s[i], g_sp.evFork, 0);
        wsplit_k<<<WN / 1024, 256, 0, g_sp.s[i]>>>(wsrc[i], wh + (size_t)i * WN, wl + (size_t)i * WN, WN);
        cudaEventRecord(g_sp.evW[i], g_sp.s[i]);
        gn_kernel<<<GROUPS, 256, 0, g_sp.s[i]>>>(x + (size_t)i * CS, gamma, beta,
            hnh + (size_t)i * CS, hnl + (size_t)i * CS);
    }

    dim3 gqk(HW / 128, 8, 1);              // q + k (byoff 0)
    dim3 gv(HW / 128, 4, 1);               // v (byoff 8)
    dim3 gq1(HW / 128, CC / 128, 1);
    dim3 gs1(HW / 128, HW / 128, 1);

    const __nv_bfloat16* wph = wh + 3 * (size_t)WN;
    const __nv_bfloat16* wpl = wl + 3 * (size_t)WN;

    for (int b = 0; b < BB; b++) {
        cudaStream_t st = g_sp.s[b];
        // this stream already ordered after its own wsplit+GN; wait for other streams' weight splits
        for (int i = 0; i < 4; i++)
            if (i != b) cudaStreamWaitEvent(st, g_sp.evW[i], 0);

        const __nv_bfloat16* hnh_b = hnh + (size_t)b * CS;
        const __nv_bfloat16* hnl_b = hnl + (size_t)b * CS;
        __nv_bfloat16* qc_b = qc + (size_t)b * PS;
        __nv_bfloat16* kc_b = kc + (size_t)b * PS;
        __nv_bfloat16* vc_b = vc + (size_t)b * CS;
        __half* s_b = s + (size_t)b * SS;
        __nv_bfloat16* wc_b = wc + (size_t)b * SS;
        __nv_bfloat16* hh_b = hh + (size_t)b * CS;
        __nv_bfloat16* hl_b = hl + (size_t)b * CS;

        // q, k projections (critical path to scores)
        qkv_gemm_k<<<gqk, 256, SMEM_BF16, st>>>(wh, wl, hnh_b, hnl_b,
            qc_b, kc_b, vc_b, bq, bk, bv, dq, zq, dk, zk, dv, zv, 0);

        code_gemm_k<0><<<gs1, 256, SMEM_CODE, st>>>(qc_b, kc_b, s_b, nullptr, nullptr,
            HW, HW, CC, dq, dk, 0.044194173824159216f);

        // v projection overlaps scores / softmax of this and other streams
        qkv_gemm_k<<<gv, 256, SMEM_BF16, st>>>(wh, wl, hnh_b, hnl_b,
            qc_b, kc_b, vc_b, bq, bk, bv, dq, zq, dk, zk, dv, zv, 8);

        softmax_quant_k<<<HW, 256, 0, st>>>(s_b, wc_b, dw);

        code_gemm_k<1><<<gq1, 256, SMEM_CODE, st>>>(vc_b, wc_b, nullptr, hh_b, hl_b,
            CC, HW, HW, dv, dw, 1.0f);

        proj_gemm_k<<<gq1, 256, SMEM_BF16, st>>>(wph, wpl, hh_b, hl_b,
            out + (size_t)b * CS, CC, HW, CC, bp, x + (size_t)b * CS);

        cudaEventRecord(g_sp.evJoin[b], st);
        cudaStreamWaitEvent(0, g_sp.evJoin[b], 0);
    }
}

// round 17
// speedup vs baseline: 1.0183x; 1.0089x over previous
#include <cuda_runtime.h>
#include <cuda_bf16.h>
#include <cuda_fp16.h>
#include <stdint.h>
#include <math.h>

#define BB 4
#define CC 512
#define HW 4096
#define GROUPS 32
#define GSIZE 16

// ---------------- scratch ----------------
__device__ __half        g_s [(size_t)BB * HW * HW];
__device__ __nv_bfloat16 g_hnh[(size_t)BB * CC * HW];
__device__ __nv_bfloat16 g_hnl[(size_t)BB * CC * HW];
__device__ __nv_bfloat16 g_hh[(size_t)BB * CC * HW];
__device__ __nv_bfloat16 g_hl[(size_t)BB * CC * HW];
__device__ __nv_bfloat16 g_qc[(size_t)BB * HW * CC];
__device__ __nv_bfloat16 g_kc[(size_t)BB * HW * CC];
__device__ __nv_bfloat16 g_vc[(size_t)BB * CC * HW];
__device__ __nv_bfloat16 g_wc[(size_t)BB * HW * HW];
__device__ __nv_bfloat16 g_wh[4][CC * CC];
__device__ __nv_bfloat16 g_wl[4][CC * CC];

// ---------------- streams/events ----------------
struct StreamPack {
    cudaStream_t s[4];
    cudaEvent_t evFork, evW[4], evJoin[4];
    StreamPack() {
        for (int i = 0; i < 4; i++) cudaStreamCreateWithFlags(&s[i], cudaStreamNonBlocking);
        cudaEventCreateWithFlags(&evFork, cudaEventDisableTiming);
        for (int i = 0; i < 4; i++) cudaEventCreateWithFlags(&evW[i], cudaEventDisableTiming);
        for (int i = 0; i < 4; i++) cudaEventCreateWithFlags(&evJoin[i], cudaEventDisableTiming);
    }
};
static StreamPack g_sp;

__device__ __forceinline__ uint32_t smem_u32(const void* p) {
    return (uint32_t)__cvta_generic_to_shared(p);
}
__device__ __forceinline__ void cp16(uint32_t dst, const void* src) {
    asm volatile("cp.async.cg.shared.global [%0], [%1], 16;" :: "r"(dst), "l"(src));
}
__device__ __forceinline__ uint32_t bf16pair(float a, float b) {
    return (uint32_t)__bfloat16_as_ushort(__float2bfloat16(a)) |
           ((uint32_t)__bfloat16_as_ushort(__float2bfloat16(b)) << 16);
}
__device__ __forceinline__ void split_pack2(float a0, float a1, uint32_t& hi, uint32_t& lo) {
    __nv_bfloat16 h0 = __float2bfloat16(a0);
    __nv_bfloat16 h1 = __float2bfloat16(a1);
    __nv_bfloat16 l0 = __float2bfloat16(a0 - __bfloat162float(h0));
    __nv_bfloat16 l1 = __float2bfloat16(a1 - __bfloat162float(h1));
    hi = (uint32_t)__bfloat16_as_ushort(h0) | ((uint32_t)__bfloat16_as_ushort(h1) << 16);
    lo = (uint32_t)__bfloat16_as_ushort(l0) | ((uint32_t)__bfloat16_as_ushort(l1) << 16);
}

// ---------------- weight split ----------------
__global__ __launch_bounds__(256) void wsplit_k(
    const float* __restrict__ src, __nv_bfloat16* __restrict__ hi,
    __nv_bfloat16* __restrict__ lo, int n)
{
    const int i = (blockIdx.x * 256 + threadIdx.x) * 4;
    if (i >= n) return;
    float4 t = *(const float4*)(src + i);
    uint32_t h01, l01, h23, l23;
    split_pack2(t.x, t.y, h01, l01);
    split_pack2(t.z, t.w, h23, l23);
    *(uint2*)(hi + i) = make_uint2(h01, h23);
    *(uint2*)(lo + i) = make_uint2(l01, l23);
}

// ---------------- per-batch GroupNorm, 128 CTAs (redundant stats, L2-served) ----------------
// CTA c: group g = c>>2, writes quarter (c&3) = 4 channels. Stats over whole group
// computed identically in all 4 CTAs of a group (same loop/reduction order as before).
__global__ __launch_bounds__(256) void gn_kernel(
    const float* __restrict__ x, const float* __restrict__ gamma,
    const float* __restrict__ beta,
    __nv_bfloat16* __restrict__ oh, __nv_bfloat16* __restrict__ ol)
{
    const int g = blockIdx.x >> 2;
    const int qtr = blockIdx.x & 3;
    const size_t base = (size_t)g * GSIZE * HW;
    const int LEN4 = (GSIZE * HW) / 4;           // 16384 float4 (whole group)
    const float4* __restrict__ xin = (const float4*)(x + base);

    float s = 0.f, s2 = 0.f;
    for (int i = threadIdx.x; i < LEN4; i += 256) {
        float4 t = xin[i];
        s  += t.x + t.y + t.z + t.w;
        s2 += t.x * t.x + t.y * t.y + t.z * t.z + t.w * t.w;
    }
    __shared__ float wr1[8], wr2[8];
    __shared__ float s_mu, s_rstd;
    for (int o = 16; o; o >>= 1) {
        s  += __shfl_xor_sync(0xffffffffu, s,  o);
        s2 += __shfl_xor_sync(0xffffffffu, s2, o);
    }
    const int warp = threadIdx.x >> 5, lane = threadIdx.x & 31;
    if (lane == 0) { wr1[warp] = s; wr2[warp] = s2; }
    __syncthreads();
    if (threadIdx.x == 0) {
        float ts = 0.f, ts2 = 0.f;
        #pragma unroll
        for (int i = 0; i < 8; i++) { ts += wr1[i]; ts2 += wr2[i]; }
        const float inv_n = 1.0f / (float)(GSIZE * HW);
        float mu  = ts * inv_n;
        float var = ts2 * inv_n - mu * mu;
        s_mu = mu;
        s_rstd = 1.0f / sqrtf(var + 1e-6f);
    }
    __syncthreads();
    const float mu = s_mu, rstd = s_rstd;

    // write only this CTA's quarter: 4 channels = 4096 float4
    const int QLEN4 = LEN4 / 4;                  // 4096
    const int qoff = qtr * QLEN4;                // offset in float4 units
    for (int i = threadIdx.x; i < QLEN4; i += 256) {
        const int gi = qoff + i;
        float4 t = xin[gi];
        const int c = g * GSIZE + ((gi * 4) >> 12);
        const float ga = gamma[c] * rstd, be = beta[c];
        t.x = (t.x - mu) * ga + be;
        t.y = (t.y - mu) * ga + be;
        t.z = (t.z - mu) * ga + be;
        t.w = (t.w - mu) * ga + be;
        uint32_t h01, l01, h23, l23;
        split_pack2(t.x, t.y, h01, l01);
        split_pack2(t.z, t.w, h23, l23);
        *(uint2*)(oh + base + (size_t)gi * 4) = make_uint2(h01, h23);
        *(uint2*)(ol + base + (size_t)gi * 4) = make_uint2(l01, l23);
    }
}

// ---------------- common bf16x3 mainloop pieces ----------------
#define A_ROWB 80
#define B_ROWB 272
#define ABYTES (128 * A_ROWB)
#define BBYTES (32 * B_ROWB)
#define BUFB   (2 * ABYTES + 2 * BBYTES)
#define SMEM_BF16 (3 * BUFB)

// ---------------- QKV projection GEMM (stacked weights, byoff selects slice) ----------------
__global__ __launch_bounds__(256, 2) void qkv_gemm_k(
    const __nv_bfloat16* __restrict__ Ah_g, const __nv_bfloat16* __restrict__ Al_g,
    const __nv_bfloat16* __restrict__ Bh_g, const __nv_bfloat16* __restrict__ Bl_g,
    __nv_bfloat16* __restrict__ Qc, __nv_bfloat16* __restrict__ Kc, __nv_bfloat16* __restrict__ Vc,
    const float* __restrict__ bq, const float* __restrict__ bk, const float* __restrict__ bv,
    const float* __restrict__ dq, const float* __restrict__ zq,
    const float* __restrict__ dk, const float* __restrict__ zk,
    const float* __restrict__ dv, const float* __restrict__ zv,
    int byoff)
{
    extern __shared__ char sm[];
    const uint32_t smb = smem_u32(sm);

    const int K = CC, N = HW, M = CC;
    const int by = blockIdx.y + byoff;
    const int p = by >> 2;
    const int bm = by * 128;
    const int bmL = (by & 3) * 128;
    const int bn = blockIdx.x * 128;
    const int tid = threadIdx.x;
    const int w = tid >> 5, lane = tid & 31;
    const int wm = w >> 2, wn = w & 3;
    const int grp = lane >> 2, tig = lane & 3;

    float acc[4][4][4];
    #pragma unroll
    for (int a = 0; a < 4; a++)
        #pragma unroll
        for (int b = 0; b < 4; b++)
            #pragma unroll
            for (int c = 0; c < 4; c++) acc[a][b][c] = 0.f;

    const uint32_t a_lane = (uint32_t)(lane & 15) * A_ROWB + (uint32_t)(lane >> 4) * 16;
    const uint32_t b_lane = (uint32_t)(lane & 15) * B_ROWB;

    const int nst = K >> 5;

#define PJ_FILL(ST) do {                                                       \
        const uint32_t _b = smb + (uint32_t)((ST) % 3) * BUFB;                 \
        const int _k0 = (ST) << 5;                                             \
        _Pragma("unroll")                                                      \
        for (int _j = 0; _j < 2; _j++) {                                       \
            const int _id = tid + 256 * _j;                                    \
            const int _ar = _id >> 2, _as = _id & 3;                           \
            const size_t _ag = (size_t)(bm + _ar) * K + _k0 + _as * 8;         \
            cp16(_b + (uint32_t)(_ar * A_ROWB + _as * 16), Ah_g + _ag);        \
            cp16(_b + ABYTES + (uint32_t)(_ar * A_ROWB + _as * 16), Al_g + _ag); \
            const int _br = _id >> 4, _bs = _id & 15;                          \
            const size_t _bg = (size_t)(_k0 + _br) * N + bn + _bs * 8;         \
            cp16(_b + 2 * ABYTES + (uint32_t)(_br * B_ROWB + _bs * 16), Bh_g + _bg); \
            cp16(_b + 2 * ABYTES + BBYTES + (uint32_t)(_br * B_ROWB + _bs * 16), Bl_g + _bg); \
        }                                                                      \
    } while (0)

    PJ_FILL(0);
    asm volatile("cp.async.commit_group;");
    if (nst > 1) PJ_FILL(1);
    asm volatile("cp.async.commit_group;");

    for (int st = 0; st < nst; st++) {
        asm volatile("cp.async.wait_group 1;");
        __syncthreads();
        if (st + 2 < nst) PJ_FILL(st + 2);
        asm volatile("cp.async.commit_group;");

        const uint32_t aho = smb + (uint32_t)(st % 3) * BUFB;
        const uint32_t bho = aho + 2 * ABYTES;

        #pragma unroll
        for (int kc = 0; kc < 2; kc++) {
            uint32_t bhf[4][2], blf[4][2];
            #pragma unroll
            for (int fn = 0; fn < 4; fn++) {
                const uint32_t addr = bho + kc * 16 * B_ROWB + b_lane + (uint32_t)(wn * 64 + fn * 16);
                asm volatile("ldmatrix.sync.aligned.m8n8.x2.trans.shared.b16 {%0,%1},[%2];"
                             : "=r"(bhf[fn][0]), "=r"(bhf[fn][1]) : "r"(addr));
                asm volatile("ldmatrix.sync.aligned.m8n8.x2.trans.shared.b16 {%0,%1},[%2];"
                             : "=r"(blf[fn][0]), "=r"(blf[fn][1]) : "r"(addr + BBYTES));
            }
            #pragma unroll
            for (int fm = 0; fm < 4; fm++) {
                const uint32_t aaddr = aho + (uint32_t)((wm * 64 + fm * 16) * A_ROWB) + kc * 32 + a_lane;
                uint32_t ah[4], al[4];
                asm volatile("ldmatrix.sync.aligned.m8n8.x4.shared.b16 {%0,%1,%2,%3},[%4];"
                             : "=r"(ah[0]), "=r"(ah[1]), "=r"(ah[2]), "=r"(ah[3]) : "r"(aaddr));
                asm volatile("ldmatrix.sync.aligned.m8n8.x4.shared.b16 {%0,%1,%2,%3},[%4];"
                             : "=r"(al[0]), "=r"(al[1]), "=r"(al[2]), "=r"(al[3]) : "r"(aaddr + ABYTES));
                #pragma unroll
                for (int fn = 0; fn < 4; fn++) {
                    float* d = acc[fm][fn];
                    asm volatile(
                        "mma.sync.aligned.m16n8k16.row.col.f32.bf16.bf16.f32 "
                        "{%0,%1,%2,%3},{%4,%5,%6,%7},{%8,%9},{%0,%1,%2,%3};\n"
                        : "+f"(d[0]), "+f"(d[1]), "+f"(d[2]), "+f"(d[3])
                        : "r"(ah[0]), "r"(ah[1]), "r"(ah[2]), "r"(ah[3]),
                          "r"(bhf[fn][0]), "r"(bhf[fn][1]));
                    asm volatile(
                        "mma.sync.aligned.m16n8k16.row.col.f32.bf16.bf16.f32 "
                        "{%0,%1,%2,%3},{%4,%5,%6,%7},{%8,%9},{%0,%1,%2,%3};\n"
                        : "+f"(d[0]), "+f"(d[1]), "+f"(d[2]), "+f"(d[3])
                        : "r"(ah[0]), "r"(ah[1]), "r"(ah[2]), "r"(ah[3]),
                          "r"(blf[fn][0]), "r"(blf[fn][1]));
                    asm volatile(
                        "mma.sync.aligned.m16n8k16.row.col.f32.bf16.bf16.f32 "
                        "{%0,%1,%2,%3},{%4,%5,%6,%7},{%8,%9},{%0,%1,%2,%3};\n"
                        : "+f"(d[0]), "+f"(d[1]), "+f"(d[2]), "+f"(d[3])
                        : "r"(al[0]), "r"(al[1]), "r"(al[2]), "r"(al[3]),
                          "r"(bhf[fn][0]), "r"(bhf[fn][1]));
                }
            }
        }
        __syncthreads();
    }
#undef PJ_FILL

    const float delta = (p == 0) ? *dq : (p == 1) ? *dk : *dv;
    const float zp    = (p == 0) ? *zq : (p == 1) ? *zk : *zv;
    const float* bias = (p == 0) ? bq : (p == 1) ? bk : bv;
    const float invd = 1.0f / delta;

    if (p == 2) {
        __nv_bfloat16* Cb = Vc;
        #pragma unroll
        for (int fm = 0; fm < 4; fm++) {
            const int r1 = wm * 64 + fm * 16 + grp;
            const int r2 = r1 + 8;
            const float b1v = bias[bmL + r1];
            const float b2v = bias[bmL + r2];
            #pragma unroll
            for (int fn = 0; fn < 4; fn++) {
                const int c = wn * 32 + fn * 8 + tig * 2;
                const float* d = acc[fm][fn];
                float q0 = fminf(fmaxf(rintf((d[0] + b1v) * invd) + zp, 0.f), 255.f) - zp;
                float q1 = fminf(fmaxf(rintf((d[1] + b1v) * invd) + zp, 0.f), 255.f) - zp;
                float q2 = fminf(fmaxf(rintf((d[2] + b2v) * invd) + zp, 0.f), 255.f) - zp;
                float q3 = fminf(fmaxf(rintf((d[3] + b2v) * invd) + zp, 0.f), 255.f) - zp;
                *(uint32_t*)(Cb + (size_t)(bmL + r1) * N + bn + c) = bf16pair(q0, q1);
                *(uint32_t*)(Cb + (size_t)(bmL + r2) * N + bn + c) = bf16pair(q2, q3);
            }
        }
    } else {
        __nv_bfloat16* Cb = (p == 0) ? Qc : Kc;
        __nv_bfloat16* t16 = (__nv_bfloat16*)sm;
        #pragma unroll
        for (int fm = 0; fm < 4; fm++) {
            const int r1 = wm * 64 + fm * 16 + grp;
            const int r2 = r1 + 8;
            const float b1v = bias[bmL + r1];
            const float b2v = bias[bmL + r2];
            #pragma unroll
            for (int fn = 0; fn < 4; fn++) {
                const int c = wn * 32 + fn * 8 + tig * 2;
                const float* d = acc[fm][fn];
                float q0 = fminf(fmaxf(rintf((d[0] + b1v) * invd) + zp, 0.f), 255.f) - zp;
                float q1 = fminf(fmaxf(rintf((d[1] + b1v) * invd) + zp, 0.f), 255.f) - zp;
                float q2 = fminf(fmaxf(rintf((d[2] + b2v) * invd) + zp, 0.f), 255.f) - zp;
                float q3 = fminf(fmaxf(rintf((d[3] + b2v) * invd) + zp, 0.f), 255.f) - zp;
                t16[(c + 0) * 136 + r1] = __float2bfloat16(q0);
                t16[(c + 1) * 136 + r1] = __float2bfloat16(q1);
                t16[(c + 0) * 136 + r2] = __float2bfloat16(q2);
                t16[(c + 1) * 136 + r2] = __float2bfloat16(q3);
            }
        }
        __syncthreads();
        #pragma unroll
        for (int it = 0; it < 8; it++) {
            const int l = tid + 256 * it;
            const int row = l >> 4;
            const int seg = l & 15;
            uint4 val = *(uint4*)(t16 + row * 136 + seg * 8);
            *(uint4*)(Cb + (size_t)(bn + row) * M + bmL + seg * 8) = val;
        }
    }
}

// ---------------- output projection GEMM ----------------
__global__ __launch_bounds__(256, 2) void proj_gemm_k(
    const __nv_bfloat16* __restrict__ Ah_g, const __nv_bfloat16* __restrict__ Al_g,
    const __nv_bfloat16* __restrict__ Bh_g, const __nv_bfloat16* __restrict__ Bl_g,
    float* __restrict__ C, int M, int N, int K,
    const float* __restrict__ bias, const float* __restrict__ resid)
{
    extern __shared__ char sm[];
    const uint32_t smb = smem_u32(sm);

    const int bm = blockIdx.y * 128;
    const int bn = blockIdx.x * 128;
    const int tid = threadIdx.x;
    const int w = tid >> 5, lane = tid & 31;
    const int wm = w >> 2, wn = w & 3;
    const int grp = lane >> 2, tig = lane & 3;

    float acc[4][4][4];
    #pragma unroll
    for (int a = 0; a < 4; a++)
        #pragma unroll
        for (int b = 0; b < 4; b++)
            #pragma unroll
            for (int c = 0; c < 4; c++) acc[a][b][c] = 0.f;

    const uint32_t a_lane = (uint32_t)(lane & 15) * A_ROWB + (uint32_t)(lane >> 4) * 16;
    const uint32_t b_lane = (uint32_t)(lane & 15) * B_ROWB;

    const int nst = K >> 5;

#define PJ_FILL(ST) do {                                                       \
        const uint32_t _b = smb + (uint32_t)((ST) % 3) * BUFB;                 \
        const int _k0 = (ST) << 5;                                             \
        _Pragma("unroll")                                                      \
        for (int _j = 0; _j < 2; _j++) {                                       \
            const int _id = tid + 256 * _j;                                    \
            const int _ar = _id >> 2, _as = _id & 3;                           \
            const size_t _ag = (size_t)(bm + _ar) * K + _k0 + _as * 8;         \
            cp16(_b + (uint32_t)(_ar * A_ROWB + _as * 16), Ah_g + _ag);        \
            cp16(_b + ABYTES + (uint32_t)(_ar * A_ROWB + _as * 16), Al_g + _ag); \
            const int _br = _id >> 4, _bs = _id & 15;                          \
            const size_t _bg = (size_t)(_k0 + _br) * N + bn + _bs * 8;         \
            cp16(_b + 2 * ABYTES + (uint32_t)(_br * B_ROWB + _bs * 16), Bh_g + _bg); \
            cp16(_b + 2 * ABYTES + BBYTES + (uint32_t)(_br * B_ROWB + _bs * 16), Bl_g + _bg); \
        }                                                                      \
    } while (0)

    PJ_FILL(0);
    asm volatile("cp.async.commit_group;");
    if (nst > 1) PJ_FILL(1);
    asm volatile("cp.async.commit_group;");

    for (int st = 0; st < nst; st++) {
        asm volatile("cp.async.wait_group 1;");
        __syncthreads();
        if (st + 2 < nst) PJ_FILL(st + 2);
        asm volatile("cp.async.commit_group;");

        const uint32_t aho = smb + (uint32_t)(st % 3) * BUFB;
        const uint32_t bho = aho + 2 * ABYTES;

        #pragma unroll
        for (int kc = 0; kc < 2; kc++) {
            uint32_t bhf[4][2], blf[4][2];
            #pragma unroll
            for (int fn = 0; fn < 4; fn++) {
                const uint32_t addr = bho + kc * 16 * B_ROWB + b_lane + (uint32_t)(wn * 64 + fn * 16);
                asm volatile("ldmatrix.sync.aligned.m8n8.x2.trans.shared.b16 {%0,%1},[%2];"
                             : "=r"(bhf[fn][0]), "=r"(bhf[fn][1]) : "r"(addr));
                asm volatile("ldmatrix.sync.aligned.m8n8.x2.trans.shared.b16 {%0,%1},[%2];"
                             : "=r"(blf[fn][0]), "=r"(blf[fn][1]) : "r"(addr + BBYTES));
            }
            #pragma unroll
            for (int fm = 0; fm < 4; fm++) {
                const uint32_t aaddr = aho + (uint32_t)((wm * 64 + fm * 16) * A_ROWB) + kc * 32 + a_lane;
                uint32_t ah[4], al[4];
                asm volatile("ldmatrix.sync.aligned.m8n8.x4.shared.b16 {%0,%1,%2,%3},[%4];"
                             : "=r"(ah[0]), "=r"(ah[1]), "=r"(ah[2]), "=r"(ah[3]) : "r"(aaddr));
                asm volatile("ldmatrix.sync.aligned.m8n8.x4.shared.b16 {%0,%1,%2,%3},[%4];"
                             : "=r"(al[0]), "=r"(al[1]), "=r"(al[2]), "=r"(al[3]) : "r"(aaddr + ABYTES));
                #pragma unroll
                for (int fn = 0; fn < 4; fn++) {
                    float* d = acc[fm][fn];
                    asm volatile(
                        "mma.sync.aligned.m16n8k16.row.col.f32.bf16.bf16.f32 "
                        "{%0,%1,%2,%3},{%4,%5,%6,%7},{%8,%9},{%0,%1,%2,%3};\n"
                        : "+f"(d[0]), "+f"(d[1]), "+f"(d[2]), "+f"(d[3])
                        : "r"(ah[0]), "r"(ah[1]), "r"(ah[2]), "r"(ah[3]),
                          "r"(bhf[fn][0]), "r"(bhf[fn][1]));
                    asm volatile(
                        "mma.sync.aligned.m16n8k16.row.col.f32.bf16.bf16.f32 "
                        "{%0,%1,%2,%3},{%4,%5,%6,%7},{%8,%9},{%0,%1,%2,%3};\n"
                        : "+f"(d[0]), "+f"(d[1]), "+f"(d[2]), "+f"(d[3])
                        : "r"(ah[0]), "r"(ah[1]), "r"(ah[2]), "r"(ah[3]),
                          "r"(blf[fn][0]), "r"(blf[fn][1]));
                    asm volatile(
                        "mma.sync.aligned.m16n8k16.row.col.f32.bf16.bf16.f32 "
                        "{%0,%1,%2,%3},{%4,%5,%6,%7},{%8,%9},{%0,%1,%2,%3};\n"
                        : "+f"(d[0]), "+f"(d[1]), "+f"(d[2]), "+f"(d[3])
                        : "r"(al[0]), "r"(al[1]), "r"(al[2]), "r"(al[3]),
                          "r"(bhf[fn][0]), "r"(bhf[fn][1]));
                }
            }
        }
        __syncthreads();
    }
#undef PJ_FILL

    #pragma unroll
    for (int fm = 0; fm < 4; fm++) {
        const int r1 = wm * 64 + fm * 16 + grp;
        const int r2 = r1 + 8;
        const float b1v = bias[bm + r1];
        const float b2v = bias[bm + r2];
        #pragma unroll
        for (int fn = 0; fn < 4; fn++) {
            const int c = wn * 32 + fn * 8 + tig * 2;
            const float* d = acc[fm][fn];
            float2 rr1 = *(const float2*)(resid + (size_t)(bm + r1) * N + bn + c);
            float2 rr2 = *(const float2*)(resid + (size_t)(bm + r2) * N + bn + c);
            float2 o1 = make_float2(d[0] + b1v + rr1.x, d[1] + b1v + rr1.y);
            float2 o2 = make_float2(d[2] + b2v + rr2.x, d[3] + b2v + rr2.y);
            *(float2*)(C + (size_t)(bm + r1) * N + bn + c) = o1;
            *(float2*)(C + (size_t)(bm + r2) * N + bn + c) = o2;
        }
    }
}

// ---------------- bf16-code GEMM (attention GEMMs) ----------------
#define CODE_STAGE 36864
#define SMEM_CODE (3 * CODE_STAGE)

template<int OUT>
__global__ __launch_bounds__(256, 2) void code_gemm_k(
    const __nv_bfloat16* __restrict__ A, const __nv_bfloat16* __restrict__ B,
    __half* __restrict__ C, __nv_bfloat16* __restrict__ Hh, __nv_bfloat16* __restrict__ Hl,
    int M, int N, int K,
    const float* __restrict__ sc1, const float* __restrict__ sc2, float fixed)
{
    extern __shared__ char sm[];
    const uint32_t smb = smem_u32(sm);

    const int bm = blockIdx.y * 128;
    const int bn = blockIdx.x * 128;
    const int tid = threadIdx.x;
    const int w = tid >> 5, lane = tid & 31;
    const int wm = w >> 2, wn = w & 3;
    const int grp = lane >> 2, tig = lane & 3;

    float acc[4][4][4];
    #pragma unroll
    for (int a = 0; a < 4; a++)
        #pragma unroll
        for (int b = 0; b < 4; b++)
            #pragma unroll
            for (int c = 0; c < 4; c++) acc[a][b][c] = 0.f;

    const int nstage = K >> 6;

    const uint32_t a_lm = (uint32_t)((lane & 15) * 144 + (lane >> 4) * 16);
    const uint32_t b_lm = (uint32_t)((lane & 7) * 144 + ((lane >> 3) & 1) * 16);

#define CODE_FILL(ST) do {                                                    \
        const uint32_t _b = smb + (uint32_t)((ST) % 3) * CODE_STAGE;          \
        const int _k0 = (ST) << 6;                                            \
        _Pragma("unroll")                                                     \
        for (int _j = 0; _j < 4; _j++) {                                      \
            const int _id = tid + 256 * _j;                                   \
            const int _r = _id >> 3, _sg = _id & 7;                           \
            cp16(_b + (uint32_t)(_r * 144 + _sg * 16),                        \
                 A + (size_t)(bm + _r) * K + _k0 + _sg * 8);                  \
            cp16(_b + 18432u + (uint32_t)(_r * 144 + _sg * 16),               \
                 B + (size_t)(bn + _r) * K + _k0 + _sg * 8);                  \
        }                                                                     \
    } while (0)

    CODE_FILL(0);
    asm volatile("cp.async.commit_group;");
    if (nstage > 1) CODE_FILL(1);
    asm volatile("cp.async.commit_group;");

    for (int st = 0; st < nstage; st++) {
        asm volatile("cp.async.wait_group 1;");
        __syncthreads();
        if (st + 2 < nstage) CODE_FILL(st + 2);
        asm volatile("cp.async.commit_group;");

        const uint32_t abase = smb + (uint32_t)(st % 3) * CODE_STAGE;
        const uint32_t bbase = abase + 18432u;
        #pragma unroll
        for (int kc = 0; kc < 4; kc++) {
            uint32_t af[4][4], bf[4][2];
            #pragma unroll
            for (int fm = 0; fm < 4; fm++) {
                const uint32_t addr = abase + (uint32_t)((wm * 64 + fm * 16) * 144) + kc * 32 + a_lm;
                asm volatile("ldmatrix.sync.aligned.m8n8.x4.shared.b16 {%0,%1,%2,%3},[%4];"
                             : "=r"(af[fm][0]), "=r"(af[fm][1]), "=r"(af[fm][2]), "=r"(af[fm][3])
                             : "r"(addr));
            }
            #pragma unroll
            for (int fn = 0; fn < 4; fn++) {
                const uint32_t addr = bbase + (uint32_t)((wn * 32 + fn * 8) * 144) + kc * 32 + b_lm;
                asm volatile("ldmatrix.sync.aligned.m8n8.x2.shared.b16 {%0,%1},[%2];"
                             : "=r"(bf[fn][0]), "=r"(bf[fn][1]) : "r"(addr));
            }
            #pragma unroll
            for (int fm = 0; fm < 4; fm++)
                #pragma unroll
                for (int fn = 0; fn < 4; fn++) {
                    float* d = acc[fm][fn];
                    asm volatile(
                        "mma.sync.aligned.m16n8k16.row.col.f32.bf16.bf16.f32 "
                        "{%0,%1,%2,%3},{%4,%5,%6,%7},{%8,%9},{%0,%1,%2,%3};\n"
                        : "+f"(d[0]), "+f"(d[1]), "+f"(d[2]), "+f"(d[3])
                        : "r"(af[fm][0]), "r"(af[fm][1]), "r"(af[fm][2]), "r"(af[fm][3]),
                          "r"(bf[fn][0]), "r"(bf[fn][1]));
                }
        }
        __syncthreads();
    }
#undef CODE_FILL

    const float scale = (*sc1) * (*sc2) * fixed;
    #pragma unroll
    for (int fm = 0; fm < 4; fm++) {
        const int row = bm + wm * 64 + fm * 16 + grp;
        #pragma unroll
        for (int fn = 0; fn < 4; fn++) {
            const int col = bn + wn * 32 + fn * 8 + tig * 2;
            const float* d = acc[fm][fn];
            if (OUT == 0) {
                __half2 v0 = __floats2half2_rn(d[0] * scale, d[1] * scale);
                __half2 v1 = __floats2half2_rn(d[2] * scale, d[3] * scale);
                *(__half2*)(C + (size_t)row * N + col) = v0;
                *(__half2*)(C + (size_t)(row + 8) * N + col) = v1;
            } else {
                uint32_t h01, l01, h23, l23;
                split_pack2(d[0] * scale, d[1] * scale, h01, l01);
                split_pack2(d[2] * scale, d[3] * scale, h23, l23);
                *(uint32_t*)(Hh + (size_t)row * N + col) = h01;
                *(uint32_t*)(Hl + (size_t)row * N + col) = l01;
                *(uint32_t*)(Hh + (size_t)(row + 8) * N + col) = h23;
                *(uint32_t*)(Hl + (size_t)(row + 8) * N + col) = l23;
            }
        }
    }
}

// ---------------- softmax (f16 in) + quant -> bf16 codes ----------------
__global__ __launch_bounds__(256) void softmax_quant_k(
    const __half* __restrict__ S, __nv_bfloat16* __restrict__ Wc,
    const float* __restrict__ d_dw)
{
    const size_t rowoff = (size_t)blockIdx.x * HW;
    const uint4* __restrict__ r8 = (const uint4*)(S + rowoff);
    const int tid = threadIdx.x;

    float v[16];
    #pragma unroll
    for (int u = 0; u < 2; u++) {
        uint4 t = r8[tid + 256 * u];
        const uint32_t* p = (const uint32_t*)&t;
        #pragma unroll
        for (int e = 0; e < 4; e++) {
            float2 f = __half22float2(*(const __half2*)&p[e]);
            v[u * 8 + e * 2]     = f.x;
            v[u * 8 + e * 2 + 1] = f.y;
        }
    }

    float mx = -3.0e38f;
    #pragma unroll
    for (int i = 0; i < 16; i++) mx = fmaxf(mx, v[i]);

    __shared__ float wr[8];
    __shared__ float bcast;
    for (int o = 16; o; o >>= 1) mx = fmaxf(mx, __shfl_xor_sync(0xffffffffu, mx, o));
    const int warp = tid >> 5, lane = tid & 31;
    if (lane == 0) wr[warp] = mx;
    __syncthreads();
    if (tid == 0) {
        float m = wr[0];
        #pragma unroll
        for (int i = 1; i < 8; i++) m = fmaxf(m, wr[i]);
        bcast = m;
    }
    __syncthreads();
    mx = bcast;

    float sum = 0.f;
    #pragma unroll
    for (int i = 0; i < 16; i++) {
        v[i] = __expf(v[i] - mx);
        sum += v[i];
    }
    for (int o = 16; o; o >>= 1) sum += __shfl_xor_sync(0xffffffffu, sum, o);
    __syncthreads();
    if (lane == 0) wr[warp] = sum;
    __syncthreads();
    if (tid == 0) {
        float t = 0.f;
        #pragma unroll
        for (int i = 0; i < 8; i++) t += wr[i];
        bcast = t;
    }
    __syncthreads();
    const float inv = 1.0f / bcast;
    const float invdw = 1.0f / (*d_dw);

    uint2* w2 = (uint2*)(Wc + rowoff);
    #pragma unroll
    for (int u = 0; u < 4; u++) {
        const float* p = v + u * 4;
        float q0 = fminf(fmaxf(rintf(p[0] * inv * invdw), 0.f), 255.f);
        float q1 = fminf(fmaxf(rintf(p[1] * inv * invdw), 0.f), 255.f);
        float q2 = fminf(fmaxf(rintf(p[2] * inv * invdw), 0.f), 255.f);
        float q3 = fminf(fmaxf(rintf(p[3] * inv * invdw), 0.f), 255.f);
        w2[(tid + 256 * (u >> 1)) * 2 + (u & 1)] = make_uint2(bf16pair(q0, q1), bf16pair(q2, q3));
    }
}

// ---------------- launch ----------------
extern "C" void kernel_launch(void* const* d_in, const int* in_sizes, int n_in,
                              void* d_out, int out_size)
{
    const float* x     = (const float*)d_in[0];
    const float* gamma = (const float*)d_in[1];
    const float* beta  = (const float*)d_in[2];
    const float* wsrc[4] = { (const float*)d_in[3], (const float*)d_in[5],
                             (const float*)d_in[7], (const float*)d_in[9] };
    const float* bq    = (const float*)d_in[4];
    const float* bk    = (const float*)d_in[6];
    const float* bv    = (const float*)d_in[8];
    const float* bp    = (const float*)d_in[10];
    const float* dq    = (const float*)d_in[11];
    const float* zq    = (const float*)d_in[12];
    const float* dk    = (const float*)d_in[13];
    const float* zk    = (const float*)d_in[14];
    const float* dv    = (const float*)d_in[15];
    const float* zv    = (const float*)d_in[16];
    const float* dw    = (const float*)d_in[17];
    float* out = (float*)d_out;

    __half* s;
    __nv_bfloat16 *hnh, *hnl, *hh, *hl, *qc, *kc, *vc, *wc, *wh, *wl;
    cudaGetSymbolAddress((void**)&s,   g_s);
    cudaGetSymbolAddress((void**)&hnh, g_hnh);
    cudaGetSymbolAddress((void**)&hnl, g_hnl);
    cudaGetSymbolAddress((void**)&hh,  g_hh);
    cudaGetSymbolAddress((void**)&hl,  g_hl);
    cudaGetSymbolAddress((void**)&qc,  g_qc);
    cudaGetSymbolAddress((void**)&kc,  g_kc);
    cudaGetSymbolAddress((void**)&vc,  g_vc);
    cudaGetSymbolAddress((void**)&wc,  g_wc);
    cudaGetSymbolAddress((void**)&wh,  g_wh);
    cudaGetSymbolAddress((void**)&wl,  g_wl);

    cudaFuncSetAttribute(qkv_gemm_k,  cudaFuncAttributeMaxDynamicSharedMemorySize, SMEM_BF16);
    cudaFuncSetAttribute(proj_gemm_k, cudaFuncAttributeMaxDynamicSharedMemorySize, SMEM_BF16);
    cudaFuncSetAttribute(code_gemm_k<0>, cudaFuncAttributeMaxDynamicSharedMemorySize, SMEM_CODE);
    cudaFuncSetAttribute(code_gemm_k<1>, cudaFuncAttributeMaxDynamicSharedMemorySize, SMEM_CODE);

    const size_t CS = (size_t)CC * HW;
    const size_t PS = (size_t)HW * CC;
    const size_t SS = (size_t)HW * HW;
    const int WN = CC * CC;

    cudaEventRecord(g_sp.evFork, 0);

    // per-stream: weight split then this batch's GroupNorm (128 CTAs)
    for (int i = 0; i < 4; i++) {
        cudaStreamWaitEvent(g_sp.s[i], g_sp.evFork, 0);
        wsplit_k<<<WN / 1024, 256, 0, g_sp.s[i]>>>(wsrc[i], wh + (size_t)i * WN, wl + (size_t)i * WN, WN);
        cudaEventRecord(g_sp.evW[i], g_sp.s[i]);
        gn_kernel<<<GROUPS * 4, 256, 0, g_sp.s[i]>>>(x + (size_t)i * CS, gamma, beta,
            hnh + (size_t)i * CS, hnl + (size_t)i * CS);
    }

    dim3 gqk(HW / 128, 8, 1);
    dim3 gv(HW / 128, 4, 1);
    dim3 gq1(HW / 128, CC / 128, 1);
    dim3 gs1(HW / 128, HW / 128, 1);

    const __nv_bfloat16* wph = wh + 3 * (size_t)WN;
    const __nv_bfloat16* wpl = wl + 3 * (size_t)WN;

    for (int b = 0; b < BB; b++) {
        cudaStream_t st = g_sp.s[b];
        for (int i = 0; i < 4; i++)
            if (i != b) cudaStreamWaitEvent(st, g_sp.evW[i], 0);

        const __nv_bfloat16* hnh_b = hnh + (size_t)b * CS;
        const __nv_bfloat16* hnl_b = hnl + (size_t)b * CS;
        __nv_bfloat16* qc_b = qc + (size_t)b * PS;
        __nv_bfloat16* kc_b = kc + (size_t)b * PS;
        __nv_bfloat16* vc_b = vc + (size_t)b * CS;
        __half* s_b = s + (size_t)b * SS;
        __nv_bfloat16* wc_b = wc + (size_t)b * SS;
        __nv_bfloat16* hh_b = hh + (size_t)b * CS;
        __nv_bfloat16* hl_b = hl + (size_t)b * CS;

        qkv_gemm_k<<<gqk, 256, SMEM_BF16, st>>>(wh, wl, hnh_b, hnl_b,
            qc_b, kc_b, vc_b, bq, bk, bv, dq, zq, dk, zk, dv, zv, 0);

        code_gemm_k<0><<<gs1, 256, SMEM_CODE, st>>>(qc_b, kc_b, s_b, nullptr, nullptr,
            HW, HW, CC, dq, dk, 0.044194173824159216f);

        qkv_gemm_k<<<gv, 256, SMEM_BF16, st>>>(wh, wl, hnh_b, hnl_b,
            qc_b, kc_b, vc_b, bq, bk, bv, dq, zq, dk, zk, dv, zv, 8);

        softmax_quant_k<<<HW, 256, 0, st>>>(s_b, wc_b, dw);

        code_gemm_k<1><<<gq1, 256, SMEM_CODE, st>>>(vc_b, wc_b, nullptr, hh_b, hl_b,
            CC, HW, HW, dv, dw, 1.0f);

        proj_gemm_k<<<gq1, 256, SMEM_BF16, st>>>(wph, wpl, hh_b, hl_b,
            out + (size_t)b * CS, CC, HW, CC, bp, x + (size_t)b * CS);

        cudaEventRecord(g_sp.evJoin[b], st);
        cudaStreamWaitEvent(0, g_sp.evJoin[b], 0);
    }
}